// round 13
// baseline (speedup 1.0000x reference)
#include <cuda_runtime.h>
#include <cuda_fp16.h>
#include <math.h>
#include <stdint.h>

#define Bx 128
#define Nx 1023
#define Hx 256
#define Xx 256
#define Cx 10
#define Vx 32000
#define NLEAF 512
#define GH3 768      // 3*H
#define NC 1280      // 2H (f gates) + 3H (iou)
#define K2H 512      // 2*H

// ---- device-global scratch (no allocations allowed) ----
__device__ __half g_h16[(size_t)Bx * Nx * Hx];        // fp16 h (GEMM A + attention)
__device__ float g_c[(size_t)Bx * Nx * Hx];           // fp32 c
__device__ __half g_emb16[(size_t)Vx * Xx];
__device__ __half g_Wc16[NC * K2H];     // gate-interleaved [f1,f2,i,o,u]x8 groups
__device__ __half g_Wiou16[GH3 * Xx];   // gate-interleaved [i,o,u]x8 groups
__device__ float g_q[Bx * Hx];
__device__ float g_ctx[Bx * Hx];

// fast transcendentals: MUFU-based, rel err ~1e-6
__device__ __forceinline__ float sigm(float x) {
    return __fdividef(1.f, 1.f + __expf(-x));
}
__device__ __forceinline__ float ftanh(float x) {
    x = fminf(fmaxf(x, -15.f), 15.f);
    float e = __expf(2.f * x);
    return __fdividef(e - 1.f, e + 1.f);
}

#define LDSM4(r0, r1, r2, r3, addr)                                          \
    asm volatile("ldmatrix.sync.aligned.m8n8.x4.shared.b16 {%0,%1,%2,%3}, [%4];" \
                 : "=r"(r0), "=r"(r1), "=r"(r2), "=r"(r3) : "r"(addr))
#define LDSM2(r0, r1, addr)                                                  \
    asm volatile("ldmatrix.sync.aligned.m8n8.x2.shared.b16 {%0,%1}, [%2];"   \
                 : "=r"(r0), "=r"(r1) : "r"(addr))

#define HMMA(d, a, b0, b1)                                                   \
    asm volatile(                                                            \
        "mma.sync.aligned.m16n8k16.row.col.f32.f16.f16.f32 "                 \
        "{%0,%1,%2,%3}, {%4,%5,%6,%7}, {%8,%9}, {%0,%1,%2,%3};"              \
        : "+f"(d[0]), "+f"(d[1]), "+f"(d[2]), "+f"(d[3])                     \
        : "r"(a[0]), "r"(a[1]), "r"(a[2]), "r"(a[3]), "r"(b0), "r"(b1))

#define CP16(dst, src)                                                       \
    asm volatile("cp.async.cg.shared.global [%0], [%1], 16;" ::"r"(dst),     \
                 "l"(src))
#define CPCOMMIT() asm volatile("cp.async.commit_group;")
#define CPWAIT(n) asm volatile("cp.async.wait_group %0;" ::"n"(n))

__device__ __forceinline__ uint32_t smem_u32(const void* p) {
    uint32_t a;
    asm("{ .reg .u64 t; cvta.to.shared.u64 t, %1; cvt.u32.u64 %0, t; }"
        : "=r"(a) : "l"(p));
    return a;
}

// ---- fp16 mirror setup (with gate interleave) ----
__global__ void emb16_k(const float* __restrict__ emb) {
    int i = blockIdx.x * 256 + threadIdx.x;
    if (i < Vx * Xx) g_emb16[i] = __float2half(emb[i]);
}
__global__ void wiou16_k(const float* __restrict__ W_iou) {
    int i = blockIdx.x * 256 + threadIdx.x;
    if (i >= GH3 * Xx) return;
    int r = i >> 8, k = i & 255;
    int w = r % 24, gate = w >> 3, j = (r / 24) * 8 + (w & 7);
    g_Wiou16[i] = __float2half(W_iou[(gate * 256 + j) * Xx + k]);
}
__global__ void wc16_k(const float* __restrict__ Uf_W,
                       const float* __restrict__ U_iou) {
    int i = blockIdx.x * 256 + threadIdx.x;
    if (i >= NC * K2H) return;
    int r = i >> 9, k = i & 511;
    int w = r % 40, gate = w >> 3, j = (r / 40) * 8 + (w & 7);
    float v = (gate < 2) ? Uf_W[(gate * 256 + j) * K2H + k]
                         : U_iou[((gate - 2) * 256 + j) * K2H + k];
    g_Wc16[i] = __float2half(v);
}

#define ROWB 144
#define ABYTES (128 * ROWB)
#define NSTAGE 4

// ===================================================================
// Large fused GEMM+node kernel (R11 structure, unchanged).
// MODE 0 (leaf):  128x192, warp 64x48, K=256.
// MODE 1 (level): 128x160, warp 64x40, K=512.
// ===================================================================
template <int MODE>
__global__ __launch_bounds__(256, 1) void hgemm_k(
    const int* __restrict__ wordid, const float* __restrict__ c0,
    const float* __restrict__ b_iou, const float* __restrict__ Uf_b,
    int K, int ps, int shift) {
    constexpr int NBLK = MODE ? 160 : 192;
    constexpr int NI = MODE ? 5 : 6;
    constexpr int WN = MODE ? 40 : 48;
    constexpr int STAGEB = (128 + NBLK) * ROWB;
    extern __shared__ char smem[];
    const uint32_t sb = smem_u32(smem);
    const int tid = threadIdx.x, lane = tid & 31, warp = tid >> 5;
    const int rowStart = blockIdx.x * 128, colStart = blockIdx.y * NBLK;
    const int warpM = warp >> 2, warpN = warp & 3;

    const int sr = tid >> 1;
    const __half* ap;
    {
        int r = rowStart + sr;
        if (MODE == 0) {
            int b = r >> 9, l = r & 511;
            int w = wordid[b * Nx + (NLEAF - 1) + l];
            ap = g_emb16 + (size_t)w * Xx + (tid & 1) * 32;
        } else {
            int b = r >> shift, pl = r & ((1 << shift) - 1);
            ap = g_h16 + ((size_t)(b * Nx + 2 * (ps + pl) + 1)) * Hx +
                 (tid & 1) * 32;
        }
    }
    const int bcol = colStart + (tid < NBLK ? tid : 0);
    const __half* bp =
        (MODE == 0 ? (const __half*)g_Wiou16 : (const __half*)g_Wc16) +
        (size_t)bcol * K;
    const uint32_t adst0 = sb + sr * ROWB + (tid & 1) * 64;
    const uint32_t bdst0 = sb + ABYTES + (tid < NBLK ? tid : 0) * ROWB;
    const bool doB = (tid < NBLK);

    const int aRow = warpM * 64 + (lane & 7) + ((lane >> 3) & 1) * 8;
    const int aK = (lane >> 4) * 8;
    const int bRow = warpN * WN + (lane & 7) + ((lane >> 4) & 1) * 8;
    const int bK = ((lane >> 3) & 1) * 8;
    const uint32_t aA0 = sb + aRow * ROWB + aK * 2;
    const uint32_t bA0 = sb + ABYTES + bRow * ROWB + bK * 2;
    const int l15 = lane & 15;
    const uint32_t b2A0 =
        sb + ABYTES + (warpN * WN + 32 + (l15 & 7)) * ROWB + (l15 >> 3) * 16;

    float acc[4][NI][4];
#pragma unroll
    for (int mi = 0; mi < 4; mi++)
#pragma unroll
        for (int ni = 0; ni < NI; ni++)
#pragma unroll
            for (int cc = 0; cc < 4; cc++) acc[mi][ni][cc] = 0.f;

    const int nch = K / 64;

#pragma unroll
    for (int s = 0; s < 3; s++) {
        const uint32_t ad = adst0 + s * STAGEB;
        const __half* ag = ap + s * 64;
        CP16(ad, ag); CP16(ad + 16, ag + 8);
        CP16(ad + 32, ag + 16); CP16(ad + 48, ag + 24);
        if (doB) {
            const uint32_t bd = bdst0 + s * STAGEB;
            const __half* bg = bp + s * 64;
            CP16(bd, bg); CP16(bd + 16, bg + 8);
            CP16(bd + 32, bg + 16); CP16(bd + 48, bg + 24);
            CP16(bd + 64, bg + 32); CP16(bd + 80, bg + 40);
            CP16(bd + 96, bg + 48); CP16(bd + 112, bg + 56);
        }
        CPCOMMIT();
    }

    for (int ci = 0; ci < nch; ci++) {
        const int rem = nch - 1 - ci;
        if (rem >= 2) { CPWAIT(2); }
        else if (rem == 1) { CPWAIT(1); }
        else { CPWAIT(0); }
        __syncthreads();
        if (ci + 3 < nch) {
            const int s = (ci + 3) & 3;
            const uint32_t ad = adst0 + s * STAGEB;
            const __half* ag = ap + (ci + 3) * 64;
            CP16(ad, ag); CP16(ad + 16, ag + 8);
            CP16(ad + 32, ag + 16); CP16(ad + 48, ag + 24);
            if (doB) {
                const uint32_t bd = bdst0 + s * STAGEB;
                const __half* bg = bp + (ci + 3) * 64;
                CP16(bd, bg); CP16(bd + 16, bg + 8);
                CP16(bd + 32, bg + 16); CP16(bd + 48, bg + 24);
                CP16(bd + 64, bg + 32); CP16(bd + 80, bg + 40);
                CP16(bd + 96, bg + 48); CP16(bd + 112, bg + 56);
            }
            CPCOMMIT();
        }
        const int slot = ci & 3;
        const uint32_t ab = aA0 + slot * STAGEB;
        const uint32_t bb = bA0 + slot * STAGEB;
        const uint32_t bb2 = b2A0 + slot * STAGEB;
#pragma unroll
        for (int ks = 0; ks < 4; ks++) {
            uint32_t aF[4][4], bq[2 * NI];
#pragma unroll
            for (int mi = 0; mi < 4; mi++)
                LDSM4(aF[mi][0], aF[mi][1], aF[mi][2], aF[mi][3],
                      ab + mi * (16 * ROWB) + ks * 32);
            if (MODE == 0) {
                LDSM4(bq[0], bq[1], bq[2], bq[3], bb + ks * 32);
                LDSM4(bq[4], bq[5], bq[6], bq[7], bb + 16 * ROWB + ks * 32);
                LDSM4(bq[8], bq[9], bq[10], bq[11], bb + 32 * ROWB + ks * 32);
            } else {
                LDSM4(bq[0], bq[1], bq[2], bq[3], bb + ks * 32);
                LDSM4(bq[4], bq[5], bq[6], bq[7], bb + 16 * ROWB + ks * 32);
                LDSM2(bq[8], bq[9], bb2 + ks * 32);
            }
#pragma unroll
            for (int mi = 0; mi < 4; mi++)
#pragma unroll
                for (int ni = 0; ni < NI; ni++)
                    HMMA(acc[mi][ni], aF[mi], bq[2 * ni], bq[2 * ni + 1]);
        }
    }

    // fused node epilogue
    const int g = lane >> 2, tt = lane & 3;
    if (MODE == 0) {
#pragma unroll
        for (int grp = 0; grp < 2; grp++) {
            const int jb = (blockIdx.y * 8 + warpN * 2 + grp) * 8 + tt * 2;
            const float bi0 = b_iou[jb], bi1 = b_iou[jb + 1];
            const float bo0 = b_iou[256 + jb], bo1 = b_iou[257 + jb];
            const float bu0 = b_iou[512 + jb], bu1 = b_iou[513 + jb];
#pragma unroll
            for (int mi = 0; mi < 4; mi++) {
#pragma unroll
                for (int hf = 0; hf < 2; hf++) {
                    const int r = rowStart + warpM * 64 + mi * 16 + g + hf * 8;
                    const int b = r >> 9, l = r & 511;
                    const size_t idx =
                        ((size_t)(b * Nx + (NLEAF - 1) + l)) * Hx + jb;
                    const float iv0 = acc[mi][grp * 3 + 0][hf * 2 + 0] + bi0;
                    const float iv1 = acc[mi][grp * 3 + 0][hf * 2 + 1] + bi1;
                    const float ov0 = acc[mi][grp * 3 + 1][hf * 2 + 0] + bo0;
                    const float ov1 = acc[mi][grp * 3 + 1][hf * 2 + 1] + bo1;
                    const float uv0 = acc[mi][grp * 3 + 2][hf * 2 + 0] + bu0;
                    const float uv1 = acc[mi][grp * 3 + 2][hf * 2 + 1] + bu1;
                    const float2 cz = *(const float2*)(c0 + idx);
                    const float cA = sigm(iv0) * ftanh(uv0) + cz.x;
                    const float cB = sigm(iv1) * ftanh(uv1) + cz.y;
                    const float hA = sigm(ov0) * ftanh(cA);
                    const float hB = sigm(ov1) * ftanh(cB);
                    *(float2*)(g_c + idx) = make_float2(cA, cB);
                    *(__half2*)(g_h16 + idx) = __floats2half2_rn(hA, hB);
                }
            }
        }
    } else {
        const int jb = (blockIdx.y * 4 + warpN) * 8 + tt * 2;
        const float bf10 = Uf_b[jb], bf11 = Uf_b[jb + 1];
        const float bf20 = Uf_b[256 + jb], bf21 = Uf_b[257 + jb];
        const float bi0 = b_iou[jb], bi1 = b_iou[jb + 1];
        const float bo0 = b_iou[256 + jb], bo1 = b_iou[257 + jb];
        const float bu0 = b_iou[512 + jb], bu1 = b_iou[513 + jb];
        const int mask = (1 << shift) - 1;
#pragma unroll
        for (int mi = 0; mi < 4; mi++) {
#pragma unroll
            for (int hf = 0; hf < 2; hf++) {
                const int r = rowStart + warpM * 64 + mi * 16 + g + hf * 8;
                const int b = r >> shift, pl = r & mask;
                const int p = ps + pl;
                const size_t cidx = ((size_t)(b * Nx + 2 * p + 1)) * Hx + jb;
                const float2 c1 = *(const float2*)(g_c + cidx);
                const float2 c2 = *(const float2*)(g_c + cidx + Hx);
                const float f10 = sigm(acc[mi][0][hf * 2 + 0] + bf10);
                const float f11 = sigm(acc[mi][0][hf * 2 + 1] + bf11);
                const float f20 = sigm(acc[mi][1][hf * 2 + 0] + bf20);
                const float f21 = sigm(acc[mi][1][hf * 2 + 1] + bf21);
                const float cs0 = f10 * c1.x + f20 * c2.x;
                const float cs1 = f11 * c1.y + f21 * c2.y;
                const float iv0 = acc[mi][2][hf * 2 + 0] + bi0;
                const float iv1 = acc[mi][2][hf * 2 + 1] + bi1;
                const float ov0 = acc[mi][3][hf * 2 + 0] + bo0;
                const float ov1 = acc[mi][3][hf * 2 + 1] + bo1;
                const float uv0 = acc[mi][4][hf * 2 + 0] + bu0;
                const float uv1 = acc[mi][4][hf * 2 + 1] + bu1;
                const float cA = sigm(iv0) * ftanh(uv0) + cs0;
                const float cB = sigm(iv1) * ftanh(uv1) + cs1;
                const float hA = sigm(ov0) * ftanh(cA);
                const float hB = sigm(ov1) * ftanh(cB);
                const size_t pidx = ((size_t)(b * Nx + p)) * Hx + jb;
                *(float2*)(g_c + pidx) = make_float2(cA, cB);
                *(__half2*)(g_h16 + pidx) = __floats2half2_rn(hA, hB);
            }
        }
    }
}

// ===================================================================
// Small-level fused kernel: 128 threads, block 32x160, 4 warps
// (warp tile 32x40), 3-stage ring, K=512. Used for levels <= 6:
// 4x finer wave granularity, ~4x lower per-CTA serial latency;
// 2 CTAs/SM keeps 8 warps/SM.
// ===================================================================
#define SMROWS 32
#define SMSTAGE ((SMROWS + 160) * ROWB)   // 27648
#define SMEM_SMALL (3 * SMSTAGE)          // 82944

__global__ __launch_bounds__(128, 2) void hgemm_small_k(
    const float* __restrict__ b_iou, const float* __restrict__ Uf_b,
    int ps, int shift) {
    extern __shared__ char smem[];
    const uint32_t sb = smem_u32(smem);
    const int tid = threadIdx.x, lane = tid & 31, warp = tid >> 5;  // warp=N idx
    const int rowStart = blockIdx.x * SMROWS, colStart = blockIdx.y * 160;
    const int mask = (1 << shift) - 1;

    // A staging: row = tid>>2, quarter = tid&3 (16 halves = 2 CP16)
    const int sr = tid >> 2, q = tid & 3;
    const __half* ap;
    {
        int r = rowStart + sr;
        int b = r >> shift, pl = r & mask;
        ap = g_h16 + ((size_t)(b * Nx + 2 * (ps + pl) + 1)) * Hx + q * 16;
    }
    const uint32_t adst0 = sb + sr * ROWB + q * 32;
    // B staging: rows tid and tid+128 (if <160)
    const __half* bpA = g_Wc16 + (size_t)(colStart + tid) * K2H;
    const __half* bpB = g_Wc16 + (size_t)(colStart + 128 + (tid & 31)) * K2H;
    const bool doB2 = (tid < 32);
    const uint32_t ab2 = (uint32_t)SMROWS * ROWB;
    const uint32_t bdstA = sb + ab2 + tid * ROWB;
    const uint32_t bdstB = sb + ab2 + (128 + (tid & 31)) * ROWB;

    // ldmatrix bases
    const int aRow = (lane & 7) + ((lane >> 3) & 1) * 8;
    const int aK = (lane >> 4) * 8;
    const uint32_t aA0 = sb + aRow * ROWB + aK * 2;
    const int bRow = warp * 40 + (lane & 7) + ((lane >> 4) & 1) * 8;
    const int bK = ((lane >> 3) & 1) * 8;
    const uint32_t bA0 = sb + ab2 + bRow * ROWB + bK * 2;
    const int l15 = lane & 15;
    const uint32_t b2A0 =
        sb + ab2 + (warp * 40 + 32 + (l15 & 7)) * ROWB + (l15 >> 3) * 16;

    float acc[2][5][4];
#pragma unroll
    for (int mi = 0; mi < 2; mi++)
#pragma unroll
        for (int ni = 0; ni < 5; ni++)
#pragma unroll
            for (int cc = 0; cc < 4; cc++) acc[mi][ni][cc] = 0.f;

    const int nch = K2H / 64;   // 8

    // prologue: chunks 0..1 into slots 0..1
#pragma unroll
    for (int s = 0; s < 2; s++) {
        const uint32_t ad = adst0 + s * SMSTAGE;
        const __half* ag = ap + s * 64;
        CP16(ad, ag); CP16(ad + 16, ag + 8);
        const uint32_t bdA = bdstA + s * SMSTAGE;
        const __half* bgA = bpA + s * 64;
        CP16(bdA, bgA); CP16(bdA + 16, bgA + 8);
        CP16(bdA + 32, bgA + 16); CP16(bdA + 48, bgA + 24);
        CP16(bdA + 64, bgA + 32); CP16(bdA + 80, bgA + 40);
        CP16(bdA + 96, bgA + 48); CP16(bdA + 112, bgA + 56);
        if (doB2) {
            const uint32_t bdB = bdstB + s * SMSTAGE;
            const __half* bgB = bpB + s * 64;
            CP16(bdB, bgB); CP16(bdB + 16, bgB + 8);
            CP16(bdB + 32, bgB + 16); CP16(bdB + 48, bgB + 24);
            CP16(bdB + 64, bgB + 32); CP16(bdB + 80, bgB + 40);
            CP16(bdB + 96, bgB + 48); CP16(bdB + 112, bgB + 56);
        }
        CPCOMMIT();
    }

    for (int ci = 0; ci < nch; ci++) {
        if (ci + 1 < nch) { CPWAIT(1); } else { CPWAIT(0); }
        __syncthreads();
        if (ci + 2 < nch) {
            const int s = (ci + 2) % 3;
            const uint32_t ad = adst0 + s * SMSTAGE;
            const __half* ag = ap + (ci + 2) * 64;
            CP16(ad, ag); CP16(ad + 16, ag + 8);
            const uint32_t bdA = bdstA + s * SMSTAGE;
            const __half* bgA = bpA + (ci + 2) * 64;
            CP16(bdA, bgA); CP16(bdA + 16, bgA + 8);
            CP16(bdA + 32, bgA + 16); CP16(bdA + 48, bgA + 24);
            CP16(bdA + 64, bgA + 32); CP16(bdA + 80, bgA + 40);
            CP16(bdA + 96, bgA + 48); CP16(bdA + 112, bgA + 56);
            if (doB2) {
                const uint32_t bdB = bdstB + s * SMSTAGE;
                const __half* bgB = bpB + (ci + 2) * 64;
                CP16(bdB, bgB); CP16(bdB + 16, bgB + 8);
                CP16(bdB + 32, bgB + 16); CP16(bdB + 48, bgB + 24);
                CP16(bdB + 64, bgB + 32); CP16(bdB + 80, bgB + 40);
                CP16(bdB + 96, bgB + 48); CP16(bdB + 112, bgB + 56);
            }
            CPCOMMIT();
        }
        const int slot = ci % 3;
        const uint32_t ab = aA0 + slot * SMSTAGE;
        const uint32_t bb = bA0 + slot * SMSTAGE;
        const uint32_t bb2 = b2A0 + slot * SMSTAGE;
#pragma unroll
        for (int ks = 0; ks < 4; ks++) {
            uint32_t aF[2][4], bq[10];
#pragma unroll
            for (int mi = 0; mi < 2; mi++)
                LDSM4(aF[mi][0], aF[mi][1], aF[mi][2], aF[mi][3],
                      ab + mi * (16 * ROWB) + ks * 32);
            LDSM4(bq[0], bq[1], bq[2], bq[3], bb + ks * 32);
            LDSM4(bq[4], bq[5], bq[6], bq[7], bb + 16 * ROWB + ks * 32);
            LDSM2(bq[8], bq[9], bb2 + ks * 32);
#pragma unroll
            for (int mi = 0; mi < 2; mi++)
#pragma unroll
                for (int ni = 0; ni < 5; ni++)
                    HMMA(acc[mi][ni], aF[mi], bq[2 * ni], bq[2 * ni + 1]);
        }
    }

    // fused node epilogue (level form)
    const int g = lane >> 2, tt = lane & 3;
    const int jb = (blockIdx.y * 4 + warp) * 8 + tt * 2;
    const float bf10 = Uf_b[jb], bf11 = Uf_b[jb + 1];
    const float bf20 = Uf_b[256 + jb], bf21 = Uf_b[257 + jb];
    const float bi0 = b_iou[jb], bi1 = b_iou[jb + 1];
    const float bo0 = b_iou[256 + jb], bo1 = b_iou[257 + jb];
    const float bu0 = b_iou[512 + jb], bu1 = b_iou[513 + jb];
#pragma unroll
    for (int mi = 0; mi < 2; mi++) {
#pragma unroll
        for (int hf = 0; hf < 2; hf++) {
            const int r = rowStart + mi * 16 + g + hf * 8;
            const int b = r >> shift, pl = r & mask;
            const int p = ps + pl;
            const size_t cidx = ((size_t)(b * Nx + 2 * p + 1)) * Hx + jb;
            const float2 c1 = *(const float2*)(g_c + cidx);
            const float2 c2 = *(const float2*)(g_c + cidx + Hx);
            const float f10 = sigm(acc[mi][0][hf * 2 + 0] + bf10);
            const float f11 = sigm(acc[mi][0][hf * 2 + 1] + bf11);
            const float f20 = sigm(acc[mi][1][hf * 2 + 0] + bf20);
            const float f21 = sigm(acc[mi][1][hf * 2 + 1] + bf21);
            const float cs0 = f10 * c1.x + f20 * c2.x;
            const float cs1 = f11 * c1.y + f21 * c2.y;
            const float iv0 = acc[mi][2][hf * 2 + 0] + bi0;
            const float iv1 = acc[mi][2][hf * 2 + 1] + bi1;
            const float ov0 = acc[mi][3][hf * 2 + 0] + bo0;
            const float ov1 = acc[mi][3][hf * 2 + 1] + bo1;
            const float uv0 = acc[mi][4][hf * 2 + 0] + bu0;
            const float uv1 = acc[mi][4][hf * 2 + 1] + bu1;
            const float cA = sigm(iv0) * ftanh(uv0) + cs0;
            const float cB = sigm(iv1) * ftanh(uv1) + cs1;
            const float hA = sigm(ov0) * ftanh(cA);
            const float hB = sigm(ov1) * ftanh(cB);
            const size_t pidx = ((size_t)(b * Nx + p)) * Hx + jb;
            *(float2*)(g_c + pidx) = make_float2(cA, cB);
            *(__half2*)(g_h16 + pidx) = __floats2half2_rn(hA, hB);
        }
    }
}

// ---- q[b] = Wmem^T @ h16[b,0,:] ----
__global__ void q_k(const float* __restrict__ Wmem) {
    int b = blockIdx.x, h = threadIdx.x;
    __shared__ float dec[256];
    dec[h] = __half2float(g_h16[((size_t)(b * Nx)) * Hx + h]);
    __syncthreads();
    float s = 0.f;
#pragma unroll 4
    for (int g = 0; g < 256; g++) s += dec[g] * Wmem[g * 256 + h];
    g_q[b * Hx + h] = s;
}

// ---- per-batch fused scores + softmax + context (h from g_h16) ----
__global__ __launch_bounds__(1024) void attn_k() {
    __shared__ float q[256];
    __shared__ float sc[1024];
    __shared__ float red[32];
    __shared__ float ctxp[4][256];
    __shared__ float stat[2];
    int b = blockIdx.x, tid = threadIdx.x;
    int warp = tid >> 5, lane = tid & 31;
    if (tid < 256) q[tid] = g_q[b * Hx + tid];
    __syncthreads();
    const __half* hb = g_h16 + (size_t)b * Nx * Hx;
    for (int n = warp; n < Nx; n += 32) {
        const __half2* hr2 = (const __half2*)(hb + (size_t)n * Hx);
        float s = 0.f;
#pragma unroll
        for (int kk = 0; kk < 4; kk++) {
            int i2 = lane + kk * 32;
            float2 f = __half22float2(hr2[i2]);
            s += q[2 * i2] * f.x + q[2 * i2 + 1] * f.y;
        }
#pragma unroll
        for (int o = 16; o; o >>= 1) s += __shfl_xor_sync(0xffffffffu, s, o);
        if (lane == 0) sc[n] = s;
    }
    __syncthreads();
    float sraw = (tid < Nx) ? sc[tid] : -3.4e38f;
    float v = sraw;
#pragma unroll
    for (int o = 16; o; o >>= 1) v = fmaxf(v, __shfl_xor_sync(0xffffffffu, v, o));
    if (lane == 0) red[warp] = v;
    __syncthreads();
    if (warp == 0) {
        float m = red[lane];
#pragma unroll
        for (int o = 16; o; o >>= 1) m = fmaxf(m, __shfl_xor_sync(0xffffffffu, m, o));
        if (lane == 0) stat[0] = m;
    }
    __syncthreads();
    float m = stat[0];
    float e = (tid < Nx) ? __expf(sraw - m) : 0.f;
    sc[tid] = e;
    float s = e;
#pragma unroll
    for (int o = 16; o; o >>= 1) s += __shfl_xor_sync(0xffffffffu, s, o);
    if (lane == 0) red[warp] = s;
    __syncthreads();
    if (warp == 0) {
        float S = red[lane];
#pragma unroll
        for (int o = 16; o; o >>= 1) S += __shfl_xor_sync(0xffffffffu, S, o);
        if (lane == 0) stat[1] = S;
    }
    __syncthreads();
    float Sinv = __fdividef(1.f, stat[1]);
    int grp = tid >> 8, j = tid & 255;
    float p = 0.f;
    for (int n = grp; n < Nx; n += 4)
        p += sc[n] * __half2float(hb[(size_t)n * Hx + j]);
    ctxp[grp][j] = p;
    __syncthreads();
    if (tid < 256) {
        g_ctx[b * Hx + tid] =
            (ctxp[0][tid] + ctxp[1][tid] + ctxp[2][tid] + ctxp[3][tid]) * Sinv;
    }
}

// ---- head ----
__global__ void final_k(const float* __restrict__ wh_W,
                        const float* __restrict__ wh_b,
                        const float* __restrict__ lin_W,
                        const float* __restrict__ lin_b,
                        float* __restrict__ out) {
    int b = blockIdx.x, tid = threadIdx.x;
    int warp = tid >> 5, lane = tid & 31;
    __shared__ float ctx[256];
    __shared__ float hid[256];
    ctx[tid] = g_ctx[b * Hx + tid];
    __syncthreads();
    for (int h = warp; h < 256; h += 8) {
        const float* wr = wh_W + (size_t)h * 256;
        float s = 0.f;
#pragma unroll
        for (int kk = 0; kk < 8; kk++) s += ctx[lane + kk * 32] * wr[lane + kk * 32];
#pragma unroll
        for (int o = 16; o; o >>= 1) s += __shfl_xor_sync(0xffffffffu, s, o);
        if (lane == 0) hid[h] = fmaxf(s + wh_b[h], 0.f);
    }
    __syncthreads();
    if (warp == 0) {
        for (int cc = 0; cc < Cx; cc++) {
            const float* lr = lin_W + (size_t)cc * 256;
            float s = 0.f;
#pragma unroll
            for (int kk = 0; kk < 8; kk++) s += hid[lane + kk * 32] * lr[lane + kk * 32];
#pragma unroll
            for (int o = 16; o; o >>= 1) s += __shfl_xor_sync(0xffffffffu, s, o);
            if (lane == 0) out[b * Cx + cc] = s + lin_b[cc];
        }
    }
}

extern "C" void kernel_launch(void* const* d_in, const int* in_sizes, int n_in,
                              void* d_out, int out_size) {
    const int* wordid   = (const int*)d_in[0];
    const float* c0     = (const float*)d_in[2];
    const float* emb    = (const float*)d_in[3];
    const float* W_iou  = (const float*)d_in[4];
    const float* U_iou  = (const float*)d_in[5];
    const float* b_iou  = (const float*)d_in[6];
    const float* Uf_W   = (const float*)d_in[7];
    const float* Uf_b   = (const float*)d_in[8];
    const float* Wmem   = (const float*)d_in[9];
    const float* wh_W   = (const float*)d_in[10];
    const float* wh_b   = (const float*)d_in[11];
    const float* lin_W  = (const float*)d_in[12];
    const float* lin_b  = (const float*)d_in[13];
    float* out = (float*)d_out;
    (void)in_sizes; (void)n_in; (void)out_size;

    const int SMEM0 = NSTAGE * (128 + 192) * ROWB;   // 184320
    const int SMEM1 = NSTAGE * (128 + 160) * ROWB;   // 165888
    cudaFuncSetAttribute(hgemm_k<0>, cudaFuncAttributeMaxDynamicSharedMemorySize,
                         SMEM0);
    cudaFuncSetAttribute(hgemm_k<1>, cudaFuncAttributeMaxDynamicSharedMemorySize,
                         SMEM1);
    cudaFuncSetAttribute(hgemm_small_k,
                         cudaFuncAttributeMaxDynamicSharedMemorySize, SMEM_SMALL);

    // fp16 mirrors (gate-interleaved weights)
    emb16_k<<<(Vx * Xx + 255) / 256, 256>>>(emb);
    wiou16_k<<<(GH3 * Xx + 255) / 256, 256>>>(W_iou);
    wc16_k<<<(NC * K2H + 255) / 256, 256>>>(Uf_W, U_iou);

    // Leaves fused
    hgemm_k<0><<<dim3(Bx * NLEAF / 128, GH3 / 192), 256, SMEM0>>>(
        wordid, c0, b_iou, Uf_b, Xx, 0, 0);

    // Tree levels (serial): large kernel for 8-7, small-tile for 6-0
    for (int level = 8; level >= 7; level--) {
        int npar = 1 << level, ps = npar - 1;
        hgemm_k<1><<<dim3(npar, NC / 160), 256, SMEM1>>>(
            nullptr, nullptr, b_iou, Uf_b, K2H, ps, level);
    }
    for (int level = 6; level >= 0; level--) {
        int npar = 1 << level, ps = npar - 1;
        hgemm_small_k<<<dim3(4 << level, NC / 160), 128, SMEM_SMALL>>>(
            b_iou, Uf_b, ps, level);
    }

    // Attention + head
    q_k<<<Bx, 256>>>(Wmem);
    attn_k<<<Bx, 1024>>>();
    final_k<<<Bx, 256>>>(wh_W, wh_b, lin_W, lin_b, out);
}

// round 15
// speedup vs baseline: 1.0774x; 1.0774x over previous
#include <cuda_runtime.h>
#include <cuda_fp16.h>
#include <math.h>
#include <stdint.h>

#define Bx 128
#define Nx 1023
#define Hx 256
#define Xx 256
#define Cx 10
#define Vx 32000
#define NLEAF 512
#define GH3 768      // 3*H
#define NC 1280      // 2H (f gates) + 3H (iou)
#define K2H 512      // 2*H

// ---- device-global scratch (no allocations allowed) ----
__device__ __half g_h16[(size_t)Bx * Nx * Hx];        // fp16 h (GEMM A + attention)
__device__ float g_c[(size_t)Bx * Nx * Hx];           // fp32 c
__device__ __half g_emb16[(size_t)Vx * Xx];
__device__ __half g_tab[(size_t)Vx * GH3];            // emb @ W_iou^T (interleaved)
__device__ __half g_Wc16[NC * K2H];     // gate-interleaved [f1,f2,i,o,u]x8 groups
__device__ __half g_Wiou16[GH3 * Xx];   // gate-interleaved [i,o,u]x8 groups
__device__ float g_q[Bx * Hx];
__device__ float g_ctx[Bx * Hx];

// fast transcendentals: MUFU-based, rel err ~1e-6
__device__ __forceinline__ float sigm(float x) {
    return __fdividef(1.f, 1.f + __expf(-x));
}
__device__ __forceinline__ float ftanh(float x) {
    x = fminf(fmaxf(x, -15.f), 15.f);
    float e = __expf(2.f * x);
    return __fdividef(e - 1.f, e + 1.f);
}

#define LDSM4(r0, r1, r2, r3, addr)                                          \
    asm volatile("ldmatrix.sync.aligned.m8n8.x4.shared.b16 {%0,%1,%2,%3}, [%4];" \
                 : "=r"(r0), "=r"(r1), "=r"(r2), "=r"(r3) : "r"(addr))
#define LDSM2(r0, r1, addr)                                                  \
    asm volatile("ldmatrix.sync.aligned.m8n8.x2.shared.b16 {%0,%1}, [%2];"   \
                 : "=r"(r0), "=r"(r1) : "r"(addr))

#define HMMA(d, a, b0, b1)                                                   \
    asm volatile(                                                            \
        "mma.sync.aligned.m16n8k16.row.col.f32.f16.f16.f32 "                 \
        "{%0,%1,%2,%3}, {%4,%5,%6,%7}, {%8,%9}, {%0,%1,%2,%3};"              \
        : "+f"(d[0]), "+f"(d[1]), "+f"(d[2]), "+f"(d[3])                     \
        : "r"(a[0]), "r"(a[1]), "r"(a[2]), "r"(a[3]), "r"(b0), "r"(b1))

#define CP16(dst, src)                                                       \
    asm volatile("cp.async.cg.shared.global [%0], [%1], 16;" ::"r"(dst),     \
                 "l"(src))
#define CPCOMMIT() asm volatile("cp.async.commit_group;")
#define CPWAIT(n) asm volatile("cp.async.wait_group %0;" ::"n"(n))

__device__ __forceinline__ uint32_t smem_u32(const void* p) {
    uint32_t a;
    asm("{ .reg .u64 t; cvta.to.shared.u64 t, %1; cvt.u32.u64 %0, t; }"
        : "=r"(a) : "l"(p));
    return a;
}

// ---- fp16 mirror setup (with gate interleave) ----
__global__ void emb16_k(const float* __restrict__ emb) {
    int i = blockIdx.x * 256 + threadIdx.x;
    if (i < Vx * Xx) g_emb16[i] = __float2half(emb[i]);
}
__global__ void wiou16_k(const float* __restrict__ W_iou) {
    int i = blockIdx.x * 256 + threadIdx.x;
    if (i >= GH3 * Xx) return;
    int r = i >> 8, k = i & 255;
    int w = r % 24, gate = w >> 3, j = (r / 24) * 8 + (w & 7);
    g_Wiou16[i] = __float2half(W_iou[(gate * 256 + j) * Xx + k]);
}
__global__ void wc16_k(const float* __restrict__ Uf_W,
                       const float* __restrict__ U_iou) {
    int i = blockIdx.x * 256 + threadIdx.x;
    if (i >= NC * K2H) return;
    int r = i >> 9, k = i & 511;
    int w = r % 40, gate = w >> 3, j = (r / 40) * 8 + (w & 7);
    float v = (gate < 2) ? Uf_W[(gate * 256 + j) * K2H + k]
                         : U_iou[((gate - 2) * 256 + j) * K2H + k];
    g_Wc16[i] = __float2half(v);
}

#define ROWB 144
#define ABYTES (128 * ROWB)
#define NSTAGE 4

// ===================================================================
// Fused FP16 tensor GEMM (R11 structure).
// MODE 0 (table): A = g_emb16 rows direct (M=32000), K=256, NBLK=192;
//                 epilogue writes fp16 preacts to g_tab (no node math).
// MODE 1 (level): A = child h16 rows, K=512, NBLK=160; fused node
//                 epilogue writes g_c / g_h16.
// ===================================================================
template <int MODE>
__global__ __launch_bounds__(256, 1) void hgemm_k(
    const float* __restrict__ b_iou, const float* __restrict__ Uf_b,
    int K, int ps, int shift) {
    constexpr int NBLK = MODE ? 160 : 192;
    constexpr int NI = MODE ? 5 : 6;
    constexpr int WN = MODE ? 40 : 48;
    constexpr int STAGEB = (128 + NBLK) * ROWB;
    extern __shared__ char smem[];
    const uint32_t sb = smem_u32(smem);
    const int tid = threadIdx.x, lane = tid & 31, warp = tid >> 5;
    const int rowStart = blockIdx.x * 128, colStart = blockIdx.y * NBLK;
    const int warpM = warp >> 2, warpN = warp & 3;

    const int sr = tid >> 1;
    const __half* ap;
    {
        int r = rowStart + sr;
        if (MODE == 0) {
            ap = g_emb16 + (size_t)r * Xx + (tid & 1) * 32;
        } else {
            int b = r >> shift, pl = r & ((1 << shift) - 1);
            ap = g_h16 + ((size_t)(b * Nx + 2 * (ps + pl) + 1)) * Hx +
                 (tid & 1) * 32;
        }
    }
    const int bcol = colStart + (tid < NBLK ? tid : 0);
    const __half* bp =
        (MODE == 0 ? (const __half*)g_Wiou16 : (const __half*)g_Wc16) +
        (size_t)bcol * K;
    const uint32_t adst0 = sb + sr * ROWB + (tid & 1) * 64;
    const uint32_t bdst0 = sb + ABYTES + (tid < NBLK ? tid : 0) * ROWB;
    const bool doB = (tid < NBLK);

    const int aRow = warpM * 64 + (lane & 7) + ((lane >> 3) & 1) * 8;
    const int aK = (lane >> 4) * 8;
    const int bRow = warpN * WN + (lane & 7) + ((lane >> 4) & 1) * 8;
    const int bK = ((lane >> 3) & 1) * 8;
    const uint32_t aA0 = sb + aRow * ROWB + aK * 2;
    const uint32_t bA0 = sb + ABYTES + bRow * ROWB + bK * 2;
    const int l15 = lane & 15;
    const uint32_t b2A0 =
        sb + ABYTES + (warpN * WN + 32 + (l15 & 7)) * ROWB + (l15 >> 3) * 16;

    float acc[4][NI][4];
#pragma unroll
    for (int mi = 0; mi < 4; mi++)
#pragma unroll
        for (int ni = 0; ni < NI; ni++)
#pragma unroll
            for (int cc = 0; cc < 4; cc++) acc[mi][ni][cc] = 0.f;

    const int nch = K / 64;

#pragma unroll
    for (int s = 0; s < 3; s++) {
        const uint32_t ad = adst0 + s * STAGEB;
        const __half* ag = ap + s * 64;
        CP16(ad, ag); CP16(ad + 16, ag + 8);
        CP16(ad + 32, ag + 16); CP16(ad + 48, ag + 24);
        if (doB) {
            const uint32_t bd = bdst0 + s * STAGEB;
            const __half* bg = bp + s * 64;
            CP16(bd, bg); CP16(bd + 16, bg + 8);
            CP16(bd + 32, bg + 16); CP16(bd + 48, bg + 24);
            CP16(bd + 64, bg + 32); CP16(bd + 80, bg + 40);
            CP16(bd + 96, bg + 48); CP16(bd + 112, bg + 56);
        }
        CPCOMMIT();
    }

    for (int ci = 0; ci < nch; ci++) {
        const int rem = nch - 1 - ci;
        if (rem >= 2) { CPWAIT(2); }
        else if (rem == 1) { CPWAIT(1); }
        else { CPWAIT(0); }
        __syncthreads();
        if (ci + 3 < nch) {
            const int s = (ci + 3) & 3;
            const uint32_t ad = adst0 + s * STAGEB;
            const __half* ag = ap + (ci + 3) * 64;
            CP16(ad, ag); CP16(ad + 16, ag + 8);
            CP16(ad + 32, ag + 16); CP16(ad + 48, ag + 24);
            if (doB) {
                const uint32_t bd = bdst0 + s * STAGEB;
                const __half* bg = bp + (ci + 3) * 64;
                CP16(bd, bg); CP16(bd + 16, bg + 8);
                CP16(bd + 32, bg + 16); CP16(bd + 48, bg + 24);
                CP16(bd + 64, bg + 32); CP16(bd + 80, bg + 40);
                CP16(bd + 96, bg + 48); CP16(bd + 112, bg + 56);
            }
            CPCOMMIT();
        }
        const int slot = ci & 3;
        const uint32_t ab = aA0 + slot * STAGEB;
        const uint32_t bb = bA0 + slot * STAGEB;
        const uint32_t bb2 = b2A0 + slot * STAGEB;
#pragma unroll
        for (int ks = 0; ks < 4; ks++) {
            uint32_t aF[4][4], bq[2 * NI];
#pragma unroll
            for (int mi = 0; mi < 4; mi++)
                LDSM4(aF[mi][0], aF[mi][1], aF[mi][2], aF[mi][3],
                      ab + mi * (16 * ROWB) + ks * 32);
            if (MODE == 0) {
                LDSM4(bq[0], bq[1], bq[2], bq[3], bb + ks * 32);
                LDSM4(bq[4], bq[5], bq[6], bq[7], bb + 16 * ROWB + ks * 32);
                LDSM4(bq[8], bq[9], bq[10], bq[11], bb + 32 * ROWB + ks * 32);
            } else {
                LDSM4(bq[0], bq[1], bq[2], bq[3], bb + ks * 32);
                LDSM4(bq[4], bq[5], bq[6], bq[7], bb + 16 * ROWB + ks * 32);
                LDSM2(bq[8], bq[9], bb2 + ks * 32);
            }
#pragma unroll
            for (int mi = 0; mi < 4; mi++)
#pragma unroll
                for (int ni = 0; ni < NI; ni++)
                    HMMA(acc[mi][ni], aF[mi], bq[2 * ni], bq[2 * ni + 1]);
        }
    }

    const int g = lane >> 2, tt = lane & 3;
    if (MODE == 0) {
        // epilogue: write fp16 preacts to g_tab (interleaved layout)
#pragma unroll
        for (int mi = 0; mi < 4; mi++)
#pragma unroll
            for (int ni = 0; ni < NI; ni++) {
                const int row = rowStart + warpM * 64 + mi * 16 + g;
                const int col = colStart + warpN * WN + ni * 8 + tt * 2;
                *(__half2*)(g_tab + (size_t)row * GH3 + col) =
                    __floats2half2_rn(acc[mi][ni][0], acc[mi][ni][1]);
                *(__half2*)(g_tab + (size_t)(row + 8) * GH3 + col) =
                    __floats2half2_rn(acc[mi][ni][2], acc[mi][ni][3]);
            }
    } else {
        const int jb = (blockIdx.y * 4 + warpN) * 8 + tt * 2;
        const float bf10 = Uf_b[jb], bf11 = Uf_b[jb + 1];
        const float bf20 = Uf_b[256 + jb], bf21 = Uf_b[257 + jb];
        const float bi0 = b_iou[jb], bi1 = b_iou[jb + 1];
        const float bo0 = b_iou[256 + jb], bo1 = b_iou[257 + jb];
        const float bu0 = b_iou[512 + jb], bu1 = b_iou[513 + jb];
        const int mask = (1 << shift) - 1;
#pragma unroll
        for (int mi = 0; mi < 4; mi++) {
#pragma unroll
            for (int hf = 0; hf < 2; hf++) {
                const int r = rowStart + warpM * 64 + mi * 16 + g + hf * 8;
                const int b = r >> shift, pl = r & mask;
                const int p = ps + pl;
                const size_t cidx = ((size_t)(b * Nx + 2 * p + 1)) * Hx + jb;
                const float2 c1 = *(const float2*)(g_c + cidx);
                const float2 c2 = *(const float2*)(g_c + cidx + Hx);
                const float f10 = sigm(acc[mi][0][hf * 2 + 0] + bf10);
                const float f11 = sigm(acc[mi][0][hf * 2 + 1] + bf11);
                const float f20 = sigm(acc[mi][1][hf * 2 + 0] + bf20);
                const float f21 = sigm(acc[mi][1][hf * 2 + 1] + bf21);
                const float cs0 = f10 * c1.x + f20 * c2.x;
                const float cs1 = f11 * c1.y + f21 * c2.y;
                const float iv0 = acc[mi][2][hf * 2 + 0] + bi0;
                const float iv1 = acc[mi][2][hf * 2 + 1] + bi1;
                const float ov0 = acc[mi][3][hf * 2 + 0] + bo0;
                const float ov1 = acc[mi][3][hf * 2 + 1] + bo1;
                const float uv0 = acc[mi][4][hf * 2 + 0] + bu0;
                const float uv1 = acc[mi][4][hf * 2 + 1] + bu1;
                const float cA = sigm(iv0) * ftanh(uv0) + cs0;
                const float cB = sigm(iv1) * ftanh(uv1) + cs1;
                const float hA = sigm(ov0) * ftanh(cA);
                const float hB = sigm(ov1) * ftanh(cB);
                const size_t pidx = ((size_t)(b * Nx + p)) * Hx + jb;
                *(float2*)(g_c + pidx) = make_float2(cA, cB);
                *(__half2*)(g_h16 + pidx) = __floats2half2_rn(hA, hB);
            }
        }
    }
}

// ===================================================================
// Leaf-from-table: gather precomputed iou preacts, apply node math.
// One thread per (leaf node, unit pair). Interleaved table layout:
// unit j -> group j>>3, cols group*24 + {0,8,16} + (j&7).
// ===================================================================
__global__ void leaf_from_tab_k(const int* __restrict__ wordid,
                                const float* __restrict__ c0,
                                const float* __restrict__ b_iou) {
    int i = blockIdx.x * 256 + threadIdx.x;
    if (i >= Bx * NLEAF * 128) return;
    const int up = i & 127;       // unit pair index
    const int rl = i >> 7;        // b*512 + l
    const int b = rl >> 9, l = rl & 511;
    const int j = up * 2;
    const int gi = j >> 3, wi = j & 7;
    const int w = wordid[b * Nx + (NLEAF - 1) + l];
    const __half* row = g_tab + (size_t)w * GH3 + gi * 24;
    const float2 fi = __half22float2(*(const __half2*)(row + wi));
    const float2 fo = __half22float2(*(const __half2*)(row + 8 + wi));
    const float2 fu = __half22float2(*(const __half2*)(row + 16 + wi));
    const float iv0 = fi.x + b_iou[j], iv1 = fi.y + b_iou[j + 1];
    const float ov0 = fo.x + b_iou[256 + j], ov1 = fo.y + b_iou[257 + j];
    const float uv0 = fu.x + b_iou[512 + j], uv1 = fu.y + b_iou[513 + j];
    const size_t idx = ((size_t)(b * Nx + (NLEAF - 1) + l)) * Hx + j;
    const float2 cz = *(const float2*)(c0 + idx);
    const float cA = sigm(iv0) * ftanh(uv0) + cz.x;
    const float cB = sigm(iv1) * ftanh(uv1) + cz.y;
    const float hA = sigm(ov0) * ftanh(cA);
    const float hB = sigm(ov1) * ftanh(cB);
    *(float2*)(g_c + idx) = make_float2(cA, cB);
    *(__half2*)(g_h16 + idx) = __floats2half2_rn(hA, hB);
}

// ---- q[b] = Wmem^T @ h16[b,0,:] ----
__global__ void q_k(const float* __restrict__ Wmem) {
    int b = blockIdx.x, h = threadIdx.x;
    __shared__ float dec[256];
    dec[h] = __half2float(g_h16[((size_t)(b * Nx)) * Hx + h]);
    __syncthreads();
    float s = 0.f;
#pragma unroll 4
    for (int g = 0; g < 256; g++) s += dec[g] * Wmem[g * 256 + h];
    g_q[b * Hx + h] = s;
}

// ---- per-batch fused scores + softmax + context (h from g_h16) ----
__global__ __launch_bounds__(1024) void attn_k() {
    __shared__ float q[256];
    __shared__ float sc[1024];
    __shared__ float red[32];
    __shared__ float ctxp[4][256];
    __shared__ float stat[2];
    int b = blockIdx.x, tid = threadIdx.x;
    int warp = tid >> 5, lane = tid & 31;
    if (tid < 256) q[tid] = g_q[b * Hx + tid];
    __syncthreads();
    const __half* hb = g_h16 + (size_t)b * Nx * Hx;
    for (int n = warp; n < Nx; n += 32) {
        const __half2* hr2 = (const __half2*)(hb + (size_t)n * Hx);
        float s = 0.f;
#pragma unroll
        for (int kk = 0; kk < 4; kk++) {
            int i2 = lane + kk * 32;
            float2 f = __half22float2(hr2[i2]);
            s += q[2 * i2] * f.x + q[2 * i2 + 1] * f.y;
        }
#pragma unroll
        for (int o = 16; o; o >>= 1) s += __shfl_xor_sync(0xffffffffu, s, o);
        if (lane == 0) sc[n] = s;
    }
    __syncthreads();
    float sraw = (tid < Nx) ? sc[tid] : -3.4e38f;
    float v = sraw;
#pragma unroll
    for (int o = 16; o; o >>= 1) v = fmaxf(v, __shfl_xor_sync(0xffffffffu, v, o));
    if (lane == 0) red[warp] = v;
    __syncthreads();
    if (warp == 0) {
        float m = red[lane];
#pragma unroll
        for (int o = 16; o; o >>= 1) m = fmaxf(m, __shfl_xor_sync(0xffffffffu, m, o));
        if (lane == 0) stat[0] = m;
    }
    __syncthreads();
    float m = stat[0];
    float e = (tid < Nx) ? __expf(sraw - m) : 0.f;
    sc[tid] = e;
    float s = e;
#pragma unroll
    for (int o = 16; o; o >>= 1) s += __shfl_xor_sync(0xffffffffu, s, o);
    if (lane == 0) red[warp] = s;
    __syncthreads();
    if (warp == 0) {
        float S = red[lane];
#pragma unroll
        for (int o = 16; o; o >>= 1) S += __shfl_xor_sync(0xffffffffu, S, o);
        if (lane == 0) stat[1] = S;
    }
    __syncthreads();
    float Sinv = __fdividef(1.f, stat[1]);
    int grp = tid >> 8, j = tid & 255;
    float p = 0.f;
    for (int n = grp; n < Nx; n += 4)
        p += sc[n] * __half2float(hb[(size_t)n * Hx + j]);
    ctxp[grp][j] = p;
    __syncthreads();
    if (tid < 256) {
        g_ctx[b * Hx + tid] =
            (ctxp[0][tid] + ctxp[1][tid] + ctxp[2][tid] + ctxp[3][tid]) * Sinv;
    }
}

// ---- head ----
__global__ void final_k(const float* __restrict__ wh_W,
                        const float* __restrict__ wh_b,
                        const float* __restrict__ lin_W,
                        const float* __restrict__ lin_b,
                        float* __restrict__ out) {
    int b = blockIdx.x, tid = threadIdx.x;
    int warp = tid >> 5, lane = tid & 31;
    __shared__ float ctx[256];
    __shared__ float hid[256];
    ctx[tid] = g_ctx[b * Hx + tid];
    __syncthreads();
    for (int h = warp; h < 256; h += 8) {
        const float* wr = wh_W + (size_t)h * 256;
        float s = 0.f;
#pragma unroll
        for (int kk = 0; kk < 8; kk++) s += ctx[lane + kk * 32] * wr[lane + kk * 32];
#pragma unroll
        for (int o = 16; o; o >>= 1) s += __shfl_xor_sync(0xffffffffu, s, o);
        if (lane == 0) hid[h] = fmaxf(s + wh_b[h], 0.f);
    }
    __syncthreads();
    if (warp == 0) {
        for (int cc = 0; cc < Cx; cc++) {
            const float* lr = lin_W + (size_t)cc * 256;
            float s = 0.f;
#pragma unroll
            for (int kk = 0; kk < 8; kk++) s += hid[lane + kk * 32] * lr[lane + kk * 32];
#pragma unroll
            for (int o = 16; o; o >>= 1) s += __shfl_xor_sync(0xffffffffu, s, o);
            if (lane == 0) out[b * Cx + cc] = s + lin_b[cc];
        }
    }
}

extern "C" void kernel_launch(void* const* d_in, const int* in_sizes, int n_in,
                              void* d_out, int out_size) {
    const int* wordid   = (const int*)d_in[0];
    const float* c0     = (const float*)d_in[2];
    const float* emb    = (const float*)d_in[3];
    const float* W_iou  = (const float*)d_in[4];
    const float* U_iou  = (const float*)d_in[5];
    const float* b_iou  = (const float*)d_in[6];
    const float* Uf_W   = (const float*)d_in[7];
    const float* Uf_b   = (const float*)d_in[8];
    const float* Wmem   = (const float*)d_in[9];
    const float* wh_W   = (const float*)d_in[10];
    const float* wh_b   = (const float*)d_in[11];
    const float* lin_W  = (const float*)d_in[12];
    const float* lin_b  = (const float*)d_in[13];
    float* out = (float*)d_out;
    (void)in_sizes; (void)n_in; (void)out_size;

    const int SMEM0 = NSTAGE * (128 + 192) * ROWB;   // 184320
    const int SMEM1 = NSTAGE * (128 + 160) * ROWB;   // 165888
    cudaFuncSetAttribute(hgemm_k<0>, cudaFuncAttributeMaxDynamicSharedMemorySize,
                         SMEM0);
    cudaFuncSetAttribute(hgemm_k<1>, cudaFuncAttributeMaxDynamicSharedMemorySize,
                         SMEM1);

    // fp16 mirrors (gate-interleaved weights)
    emb16_k<<<(Vx * Xx + 255) / 256, 256>>>(emb);
    wiou16_k<<<(GH3 * Xx + 255) / 256, 256>>>(W_iou);
    wc16_k<<<(NC * K2H + 255) / 256, 256>>>(Uf_W, U_iou);

    // Table: tab = emb @ W_iou^T  (M=32000, N=768, K=256; 2x fewer flops
    // than per-leaf GEMM since each word is used ~2x)
    hgemm_k<0><<<dim3(Vx / 128, GH3 / 192), 256, SMEM0>>>(
        nullptr, nullptr, Xx, 0, 0);

    // Leaves: gather table rows + node math
    leaf_from_tab_k<<<(Bx * NLEAF * 128 + 255) / 256, 256>>>(wordid, c0, b_iou);

    // Tree levels (serial), all large fused kernel (R11 config)
    for (int level = 8; level >= 0; level--) {
        int npar = 1 << level, ps = npar - 1;
        hgemm_k<1><<<dim3(npar, NC / 160), 256, SMEM1>>>(
            b_iou, Uf_b, K2H, ps, level);
    }

    // Attention + head
    q_k<<<Bx, 256>>>(Wmem);
    attn_k<<<Bx, 1024>>>();
    final_k<<<Bx, 256>>>(wh_W, wh_b, lin_W, lin_b, out);
}

// round 16
// speedup vs baseline: 1.1540x; 1.0712x over previous
#include <cuda_runtime.h>
#include <cuda_fp16.h>
#include <math.h>
#include <stdint.h>

#define Bx 128
#define Nx 1023
#define Hx 256
#define Xx 256
#define Cx 10
#define Vx 32000
#define NLEAF 512
#define GH3 768      // 3*H
#define NC 1280      // 2H (f gates) + 3H (iou)
#define K2H 512      // 2*H

// ---- device-global scratch (no allocations allowed) ----
__device__ __half g_h16[(size_t)Bx * Nx * Hx];        // fp16 h (GEMM A + attention)
__device__ float g_c[(size_t)Bx * Nx * Hx];           // fp32 c
__device__ __half g_emb16[(size_t)Vx * Xx];
__device__ __half g_tab[(size_t)Vx * GH3];            // emb @ W_iou^T (interleaved)
__device__ __half g_Wc16[NC * K2H];     // gate-interleaved [f1,f2,i,o,u]x8 groups
__device__ __half g_Wiou16[GH3 * Xx];   // gate-interleaved [i,o,u]x8 groups
__device__ int g_bar;                   // device-wide barrier counter

// fast transcendentals: MUFU-based, rel err ~1e-6
__device__ __forceinline__ float sigm(float x) {
    return __fdividef(1.f, 1.f + __expf(-x));
}
__device__ __forceinline__ float ftanh(float x) {
    x = fminf(fmaxf(x, -15.f), 15.f);
    float e = __expf(2.f * x);
    return __fdividef(e - 1.f, e + 1.f);
}

#define LDSM4(r0, r1, r2, r3, addr)                                          \
    asm volatile("ldmatrix.sync.aligned.m8n8.x4.shared.b16 {%0,%1,%2,%3}, [%4];" \
                 : "=r"(r0), "=r"(r1), "=r"(r2), "=r"(r3) : "r"(addr))
#define LDSM2(r0, r1, addr)                                                  \
    asm volatile("ldmatrix.sync.aligned.m8n8.x2.shared.b16 {%0,%1}, [%2];"   \
                 : "=r"(r0), "=r"(r1) : "r"(addr))

#define HMMA(d, a, b0, b1)                                                   \
    asm volatile(                                                            \
        "mma.sync.aligned.m16n8k16.row.col.f32.f16.f16.f32 "                 \
        "{%0,%1,%2,%3}, {%4,%5,%6,%7}, {%8,%9}, {%0,%1,%2,%3};"              \
        : "+f"(d[0]), "+f"(d[1]), "+f"(d[2]), "+f"(d[3])                     \
        : "r"(a[0]), "r"(a[1]), "r"(a[2]), "r"(a[3]), "r"(b0), "r"(b1))

#define CP16(dst, src)                                                       \
    asm volatile("cp.async.cg.shared.global [%0], [%1], 16;" ::"r"(dst),     \
                 "l"(src))
#define CPCOMMIT() asm volatile("cp.async.commit_group;")
#define CPWAIT(n) asm volatile("cp.async.wait_group %0;" ::"n"(n))

__device__ __forceinline__ uint32_t smem_u32(const void* p) {
    uint32_t a;
    asm("{ .reg .u64 t; cvta.to.shared.u64 t, %1; cvt.u32.u64 %0, t; }"
        : "=r"(a) : "l"(p));
    return a;
}

// ---- fp16 mirror setup (with gate interleave) ----
__global__ void emb16_k(const float* __restrict__ emb) {
    int i = blockIdx.x * 256 + threadIdx.x;
    if (i < Vx * Xx) g_emb16[i] = __float2half(emb[i]);
}
__global__ void wiou16_k(const float* __restrict__ W_iou) {
    int i = blockIdx.x * 256 + threadIdx.x;
    if (i >= GH3 * Xx) return;
    int r = i >> 8, k = i & 255;
    int w = r % 24, gate = w >> 3, j = (r / 24) * 8 + (w & 7);
    g_Wiou16[i] = __float2half(W_iou[(gate * 256 + j) * Xx + k]);
}
__global__ void wc16_k(const float* __restrict__ Uf_W,
                       const float* __restrict__ U_iou) {
    int i = blockIdx.x * 256 + threadIdx.x;
    if (i >= NC * K2H) return;
    int r = i >> 9, k = i & 511;
    int w = r % 40, gate = w >> 3, j = (r / 40) * 8 + (w & 7);
    float v = (gate < 2) ? Uf_W[(gate * 256 + j) * K2H + k]
                         : U_iou[((gate - 2) * 256 + j) * K2H + k];
    g_Wc16[i] = __float2half(v);
}
__global__ void reset_bar_k() { g_bar = 0; }

#define ROWB 144
#define ABYTES (128 * ROWB)
#define NSTAGE 4

// ===================================================================
// Level GEMM+node body (shared by per-level kernel and persistent
// small-levels kernel). NBLK=160, warp 64x40, K=512, 4-stage ring.
// ===================================================================
__device__ __forceinline__ void level_body(
    char* smem, const float* __restrict__ b_iou,
    const float* __restrict__ Uf_b, int mtile, int ntile, int ps, int shift) {
    constexpr int NBLK = 160;
    constexpr int NI = 5;
    constexpr int WN = 40;
    constexpr int STAGEB = (128 + NBLK) * ROWB;
    const uint32_t sb = smem_u32(smem);
    const int tid = threadIdx.x, lane = tid & 31, warp = tid >> 5;
    const int rowStart = mtile * 128, colStart = ntile * NBLK;
    const int warpM = warp >> 2, warpN = warp & 3;
    const int mask = (1 << shift) - 1;

    const int sr = tid >> 1;
    const __half* ap;
    {
        int r = rowStart + sr;
        int b = r >> shift, pl = r & mask;
        ap = g_h16 + ((size_t)(b * Nx + 2 * (ps + pl) + 1)) * Hx + (tid & 1) * 32;
    }
    const __half* bp = g_Wc16 + (size_t)(colStart + (tid < NBLK ? tid : 0)) * K2H;
    const uint32_t adst0 = sb + sr * ROWB + (tid & 1) * 64;
    const uint32_t bdst0 = sb + ABYTES + (tid < NBLK ? tid : 0) * ROWB;
    const bool doB = (tid < NBLK);

    const int aRow = warpM * 64 + (lane & 7) + ((lane >> 3) & 1) * 8;
    const int aK = (lane >> 4) * 8;
    const int bRow = warpN * WN + (lane & 7) + ((lane >> 4) & 1) * 8;
    const int bK = ((lane >> 3) & 1) * 8;
    const uint32_t aA0 = sb + aRow * ROWB + aK * 2;
    const uint32_t bA0 = sb + ABYTES + bRow * ROWB + bK * 2;
    const int l15 = lane & 15;
    const uint32_t b2A0 =
        sb + ABYTES + (warpN * WN + 32 + (l15 & 7)) * ROWB + (l15 >> 3) * 16;

    float acc[4][NI][4];
#pragma unroll
    for (int mi = 0; mi < 4; mi++)
#pragma unroll
        for (int ni = 0; ni < NI; ni++)
#pragma unroll
            for (int cc = 0; cc < 4; cc++) acc[mi][ni][cc] = 0.f;

    const int nch = K2H / 64;   // 8

#pragma unroll
    for (int s = 0; s < 3; s++) {
        const uint32_t ad = adst0 + s * STAGEB;
        const __half* ag = ap + s * 64;
        CP16(ad, ag); CP16(ad + 16, ag + 8);
        CP16(ad + 32, ag + 16); CP16(ad + 48, ag + 24);
        if (doB) {
            const uint32_t bd = bdst0 + s * STAGEB;
            const __half* bg = bp + s * 64;
            CP16(bd, bg); CP16(bd + 16, bg + 8);
            CP16(bd + 32, bg + 16); CP16(bd + 48, bg + 24);
            CP16(bd + 64, bg + 32); CP16(bd + 80, bg + 40);
            CP16(bd + 96, bg + 48); CP16(bd + 112, bg + 56);
        }
        CPCOMMIT();
    }

    for (int ci = 0; ci < nch; ci++) {
        const int rem = nch - 1 - ci;
        if (rem >= 2) { CPWAIT(2); }
        else if (rem == 1) { CPWAIT(1); }
        else { CPWAIT(0); }
        __syncthreads();
        if (ci + 3 < nch) {
            const int s = (ci + 3) & 3;
            const uint32_t ad = adst0 + s * STAGEB;
            const __half* ag = ap + (ci + 3) * 64;
            CP16(ad, ag); CP16(ad + 16, ag + 8);
            CP16(ad + 32, ag + 16); CP16(ad + 48, ag + 24);
            if (doB) {
                const uint32_t bd = bdst0 + s * STAGEB;
                const __half* bg = bp + (ci + 3) * 64;
                CP16(bd, bg); CP16(bd + 16, bg + 8);
                CP16(bd + 32, bg + 16); CP16(bd + 48, bg + 24);
                CP16(bd + 64, bg + 32); CP16(bd + 80, bg + 40);
                CP16(bd + 96, bg + 48); CP16(bd + 112, bg + 56);
            }
            CPCOMMIT();
        }
        const int slot = ci & 3;
        const uint32_t ab = aA0 + slot * STAGEB;
        const uint32_t bb = bA0 + slot * STAGEB;
        const uint32_t bb2 = b2A0 + slot * STAGEB;
#pragma unroll
        for (int ks = 0; ks < 4; ks++) {
            uint32_t aF[4][4], bq[2 * NI];
#pragma unroll
            for (int mi = 0; mi < 4; mi++)
                LDSM4(aF[mi][0], aF[mi][1], aF[mi][2], aF[mi][3],
                      ab + mi * (16 * ROWB) + ks * 32);
            LDSM4(bq[0], bq[1], bq[2], bq[3], bb + ks * 32);
            LDSM4(bq[4], bq[5], bq[6], bq[7], bb + 16 * ROWB + ks * 32);
            LDSM2(bq[8], bq[9], bb2 + ks * 32);
#pragma unroll
            for (int mi = 0; mi < 4; mi++)
#pragma unroll
                for (int ni = 0; ni < NI; ni++)
                    HMMA(acc[mi][ni], aF[mi], bq[2 * ni], bq[2 * ni + 1]);
        }
    }

    const int g = lane >> 2, tt = lane & 3;
    const int jb = (ntile * 4 + warpN) * 8 + tt * 2;
    const float bf10 = Uf_b[jb], bf11 = Uf_b[jb + 1];
    const float bf20 = Uf_b[256 + jb], bf21 = Uf_b[257 + jb];
    const float bi0 = b_iou[jb], bi1 = b_iou[jb + 1];
    const float bo0 = b_iou[256 + jb], bo1 = b_iou[257 + jb];
    const float bu0 = b_iou[512 + jb], bu1 = b_iou[513 + jb];
#pragma unroll
    for (int mi = 0; mi < 4; mi++) {
#pragma unroll
        for (int hf = 0; hf < 2; hf++) {
            const int r = rowStart + warpM * 64 + mi * 16 + g + hf * 8;
            const int b = r >> shift, pl = r & mask;
            const int p = ps + pl;
            const size_t cidx = ((size_t)(b * Nx + 2 * p + 1)) * Hx + jb;
            const float2 c1 = *(const float2*)(g_c + cidx);
            const float2 c2 = *(const float2*)(g_c + cidx + Hx);
            const float f10 = sigm(acc[mi][0][hf * 2 + 0] + bf10);
            const float f11 = sigm(acc[mi][0][hf * 2 + 1] + bf11);
            const float f20 = sigm(acc[mi][1][hf * 2 + 0] + bf20);
            const float f21 = sigm(acc[mi][1][hf * 2 + 1] + bf21);
            const float cs0 = f10 * c1.x + f20 * c2.x;
            const float cs1 = f11 * c1.y + f21 * c2.y;
            const float iv0 = acc[mi][2][hf * 2 + 0] + bi0;
            const float iv1 = acc[mi][2][hf * 2 + 1] + bi1;
            const float ov0 = acc[mi][3][hf * 2 + 0] + bo0;
            const float ov1 = acc[mi][3][hf * 2 + 1] + bo1;
            const float uv0 = acc[mi][4][hf * 2 + 0] + bu0;
            const float uv1 = acc[mi][4][hf * 2 + 1] + bu1;
            const float cA = sigm(iv0) * ftanh(uv0) + cs0;
            const float cB = sigm(iv1) * ftanh(uv1) + cs1;
            const float hA = sigm(ov0) * ftanh(cA);
            const float hB = sigm(ov1) * ftanh(cB);
            const size_t pidx = ((size_t)(b * Nx + p)) * Hx + jb;
            *(float2*)(g_c + pidx) = make_float2(cA, cB);
            *(__half2*)(g_h16 + pidx) = __floats2half2_rn(hA, hB);
        }
    }
}

// ---- per-level kernel (levels 8..5) ----
__global__ __launch_bounds__(256, 1) void hgemm_lvl_k(
    const float* __restrict__ b_iou, const float* __restrict__ Uf_b,
    int ps, int shift) {
    extern __shared__ char smem[];
    level_body(smem, b_iou, Uf_b, blockIdx.x, blockIdx.y, ps, shift);
}

// ---- persistent kernel: levels 4..0 with device-wide phase barrier ----
// grid (16,8) = 128 CTAs, all resident (1 CTA/SM, 148 SMs).
__global__ __launch_bounds__(256, 1) void plevels_k(
    const float* __restrict__ b_iou, const float* __restrict__ Uf_b) {
    extern __shared__ char smem[];
    int target = 0;
    for (int level = 4; level >= 0; level--) {
        const int npar = 1 << level;
        if ((int)blockIdx.x < npar) {
            level_body(smem, b_iou, Uf_b, blockIdx.x, blockIdx.y,
                       npar - 1, level);
        }
        if (level > 0) {
            target += 128;
            __threadfence();
            __syncthreads();
            if (threadIdx.x == 0) {
                atomicAdd(&g_bar, 1);
                while (atomicAdd(&g_bar, 0) < target) __nanosleep(200);
            }
            __syncthreads();
            __threadfence();
        }
    }
}

// ===================================================================
// Table GEMM: tab = emb @ W_iou^T (M=32000, N=768 via NBLK=192, K=256)
// ===================================================================
__global__ __launch_bounds__(256, 1) void tabgemm_k() {
    constexpr int NBLK = 192;
    constexpr int NI = 6;
    constexpr int WN = 48;
    constexpr int STAGEB = (128 + NBLK) * ROWB;
    extern __shared__ char smem[];
    const uint32_t sb = smem_u32(smem);
    const int tid = threadIdx.x, lane = tid & 31, warp = tid >> 5;
    const int rowStart = blockIdx.x * 128, colStart = blockIdx.y * NBLK;
    const int warpM = warp >> 2, warpN = warp & 3;

    const int sr = tid >> 1;
    const __half* ap = g_emb16 + (size_t)(rowStart + sr) * Xx + (tid & 1) * 32;
    const __half* bp = g_Wiou16 + (size_t)(colStart + (tid < NBLK ? tid : 0)) * Xx;
    const uint32_t adst0 = sb + sr * ROWB + (tid & 1) * 64;
    const uint32_t bdst0 = sb + ABYTES + (tid < NBLK ? tid : 0) * ROWB;
    const bool doB = (tid < NBLK);

    const int aRow = warpM * 64 + (lane & 7) + ((lane >> 3) & 1) * 8;
    const int aK = (lane >> 4) * 8;
    const int bRow = warpN * WN + (lane & 7) + ((lane >> 4) & 1) * 8;
    const int bK = ((lane >> 3) & 1) * 8;
    const uint32_t aA0 = sb + aRow * ROWB + aK * 2;
    const uint32_t bA0 = sb + ABYTES + bRow * ROWB + bK * 2;

    float acc[4][NI][4];
#pragma unroll
    for (int mi = 0; mi < 4; mi++)
#pragma unroll
        for (int ni = 0; ni < NI; ni++)
#pragma unroll
            for (int cc = 0; cc < 4; cc++) acc[mi][ni][cc] = 0.f;

    const int nch = Xx / 64;   // 4

#pragma unroll
    for (int s = 0; s < 3; s++) {
        const uint32_t ad = adst0 + s * STAGEB;
        const __half* ag = ap + s * 64;
        CP16(ad, ag); CP16(ad + 16, ag + 8);
        CP16(ad + 32, ag + 16); CP16(ad + 48, ag + 24);
        if (doB) {
            const uint32_t bd = bdst0 + s * STAGEB;
            const __half* bg = bp + s * 64;
            CP16(bd, bg); CP16(bd + 16, bg + 8);
            CP16(bd + 32, bg + 16); CP16(bd + 48, bg + 24);
            CP16(bd + 64, bg + 32); CP16(bd + 80, bg + 40);
            CP16(bd + 96, bg + 48); CP16(bd + 112, bg + 56);
        }
        CPCOMMIT();
    }

    for (int ci = 0; ci < nch; ci++) {
        const int rem = nch - 1 - ci;
        if (rem >= 2) { CPWAIT(2); }
        else if (rem == 1) { CPWAIT(1); }
        else { CPWAIT(0); }
        __syncthreads();
        if (ci + 3 < nch) {
            const int s = (ci + 3) & 3;
            const uint32_t ad = adst0 + s * STAGEB;
            const __half* ag = ap + (ci + 3) * 64;
            CP16(ad, ag); CP16(ad + 16, ag + 8);
            CP16(ad + 32, ag + 16); CP16(ad + 48, ag + 24);
            if (doB) {
                const uint32_t bd = bdst0 + s * STAGEB;
                const __half* bg = bp + (ci + 3) * 64;
                CP16(bd, bg); CP16(bd + 16, bg + 8);
                CP16(bd + 32, bg + 16); CP16(bd + 48, bg + 24);
                CP16(bd + 64, bg + 32); CP16(bd + 80, bg + 40);
                CP16(bd + 96, bg + 48); CP16(bd + 112, bg + 56);
            }
            CPCOMMIT();
        }
        const int slot = ci & 3;
        const uint32_t ab = aA0 + slot * STAGEB;
        const uint32_t bb = bA0 + slot * STAGEB;
#pragma unroll
        for (int ks = 0; ks < 4; ks++) {
            uint32_t aF[4][4], bq[2 * NI];
#pragma unroll
            for (int mi = 0; mi < 4; mi++)
                LDSM4(aF[mi][0], aF[mi][1], aF[mi][2], aF[mi][3],
                      ab + mi * (16 * ROWB) + ks * 32);
            LDSM4(bq[0], bq[1], bq[2], bq[3], bb + ks * 32);
            LDSM4(bq[4], bq[5], bq[6], bq[7], bb + 16 * ROWB + ks * 32);
            LDSM4(bq[8], bq[9], bq[10], bq[11], bb + 32 * ROWB + ks * 32);
#pragma unroll
            for (int mi = 0; mi < 4; mi++)
#pragma unroll
                for (int ni = 0; ni < NI; ni++)
                    HMMA(acc[mi][ni], aF[mi], bq[2 * ni], bq[2 * ni + 1]);
        }
    }

    const int g = lane >> 2, tt = lane & 3;
#pragma unroll
    for (int mi = 0; mi < 4; mi++)
#pragma unroll
        for (int ni = 0; ni < NI; ni++) {
            const int row = rowStart + warpM * 64 + mi * 16 + g;
            const int col = colStart + warpN * WN + ni * 8 + tt * 2;
            *(__half2*)(g_tab + (size_t)row * GH3 + col) =
                __floats2half2_rn(acc[mi][ni][0], acc[mi][ni][1]);
            *(__half2*)(g_tab + (size_t)(row + 8) * GH3 + col) =
                __floats2half2_rn(acc[mi][ni][2], acc[mi][ni][3]);
        }
}

// ===================================================================
// Leaf-from-table: gather precomputed iou preacts, apply node math.
// ===================================================================
__global__ void leaf_from_tab_k(const int* __restrict__ wordid,
                                const float* __restrict__ c0,
                                const float* __restrict__ b_iou) {
    int i = blockIdx.x * 256 + threadIdx.x;
    if (i >= Bx * NLEAF * 128) return;
    const int up = i & 127;       // unit pair index
    const int rl = i >> 7;        // b*512 + l
    const int b = rl >> 9, l = rl & 511;
    const int j = up * 2;
    const int gi = j >> 3, wi = j & 7;
    const int w = wordid[b * Nx + (NLEAF - 1) + l];
    const __half* row = g_tab + (size_t)w * GH3 + gi * 24;
    const float2 fi = __half22float2(*(const __half2*)(row + wi));
    const float2 fo = __half22float2(*(const __half2*)(row + 8 + wi));
    const float2 fu = __half22float2(*(const __half2*)(row + 16 + wi));
    const float iv0 = fi.x + b_iou[j], iv1 = fi.y + b_iou[j + 1];
    const float ov0 = fo.x + b_iou[256 + j], ov1 = fo.y + b_iou[257 + j];
    const float uv0 = fu.x + b_iou[512 + j], uv1 = fu.y + b_iou[513 + j];
    const size_t idx = ((size_t)(b * Nx + (NLEAF - 1) + l)) * Hx + j;
    const float2 cz = *(const float2*)(c0 + idx);
    const float cA = sigm(iv0) * ftanh(uv0) + cz.x;
    const float cB = sigm(iv1) * ftanh(uv1) + cz.y;
    const float hA = sigm(ov0) * ftanh(cA);
    const float hB = sigm(ov1) * ftanh(cB);
    *(float2*)(g_c + idx) = make_float2(cA, cB);
    *(__half2*)(g_h16 + idx) = __floats2half2_rn(hA, hB);
}

// ===================================================================
// Fused attention + head: q = Wmem^T dec; scores=q.h; softmax; ctx;
// hid = relu(ctx Wh^T + b); out = hid lin^T + b.  One CTA per batch b.
// ===================================================================
__global__ __launch_bounds__(1024) void attn_all_k(
    const float* __restrict__ Wmem, const float* __restrict__ wh_W,
    const float* __restrict__ wh_b, const float* __restrict__ lin_W,
    const float* __restrict__ lin_b, float* __restrict__ out) {
    __shared__ float dec[256];
    __shared__ float q[256];
    __shared__ float sc[1024];
    __shared__ float red[32];
    __shared__ float part[4][256];
    __shared__ float stat[2];
    __shared__ float ctx[256];
    __shared__ float hid[256];
    int b = blockIdx.x, tid = threadIdx.x;
    int warp = tid >> 5, lane = tid & 31;
    const __half* hb = g_h16 + (size_t)b * Nx * Hx;
    if (tid < 256) dec[tid] = __half2float(hb[tid]);   // h[b, node 0]
    __syncthreads();
    // q[h] = sum_g dec[g] * Wmem[g*256+h], 4 partial slices
    {
        int h = tid & 255, pt = tid >> 8;
        float s = 0.f;
        const float* wm = Wmem + (size_t)(pt * 64) * 256 + h;
#pragma unroll 8
        for (int g = 0; g < 64; g++) s += dec[pt * 64 + g] * wm[g * 256];
        part[pt][h] = s;
    }
    __syncthreads();
    if (tid < 256) q[tid] = part[0][tid] + part[1][tid] + part[2][tid] + part[3][tid];
    __syncthreads();
    // scores
    for (int n = warp; n < Nx; n += 32) {
        const __half2* hr2 = (const __half2*)(hb + (size_t)n * Hx);
        float s = 0.f;
#pragma unroll
        for (int kk = 0; kk < 4; kk++) {
            int i2 = lane + kk * 32;
            float2 f = __half22float2(hr2[i2]);
            s += q[2 * i2] * f.x + q[2 * i2 + 1] * f.y;
        }
#pragma unroll
        for (int o = 16; o; o >>= 1) s += __shfl_xor_sync(0xffffffffu, s, o);
        if (lane == 0) sc[n] = s;
    }
    __syncthreads();
    float sraw = (tid < Nx) ? sc[tid] : -3.4e38f;
    float v = sraw;
#pragma unroll
    for (int o = 16; o; o >>= 1) v = fmaxf(v, __shfl_xor_sync(0xffffffffu, v, o));
    if (lane == 0) red[warp] = v;
    __syncthreads();
    if (warp == 0) {
        float m = red[lane];
#pragma unroll
        for (int o = 16; o; o >>= 1) m = fmaxf(m, __shfl_xor_sync(0xffffffffu, m, o));
        if (lane == 0) stat[0] = m;
    }
    __syncthreads();
    float m = stat[0];
    float e = (tid < Nx) ? __expf(sraw - m) : 0.f;
    sc[tid] = e;
    float s = e;
#pragma unroll
    for (int o = 16; o; o >>= 1) s += __shfl_xor_sync(0xffffffffu, s, o);
    if (lane == 0) red[warp] = s;
    __syncthreads();
    if (warp == 0) {
        float S = red[lane];
#pragma unroll
        for (int o = 16; o; o >>= 1) S += __shfl_xor_sync(0xffffffffu, S, o);
        if (lane == 0) stat[1] = S;
    }
    __syncthreads();
    float Sinv = __fdividef(1.f, stat[1]);
    {
        int grp = tid >> 8, j = tid & 255;
        float p = 0.f;
        for (int n = grp; n < Nx; n += 4)
            p += sc[n] * __half2float(hb[(size_t)n * Hx + j]);
        part[grp][j] = p;
    }
    __syncthreads();
    if (tid < 256)
        ctx[tid] = (part[0][tid] + part[1][tid] + part[2][tid] + part[3][tid]) * Sinv;
    __syncthreads();
    // head
    for (int h = warp; h < 256; h += 32) {
        const float* wr = wh_W + (size_t)h * 256;
        float s2 = 0.f;
#pragma unroll
        for (int kk = 0; kk < 8; kk++) s2 += ctx[lane + kk * 32] * wr[lane + kk * 32];
#pragma unroll
        for (int o = 16; o; o >>= 1) s2 += __shfl_xor_sync(0xffffffffu, s2, o);
        if (lane == 0) hid[h] = fmaxf(s2 + wh_b[h], 0.f);
    }
    __syncthreads();
    if (warp == 0) {
        for (int cc = 0; cc < Cx; cc++) {
            const float* lr = lin_W + (size_t)cc * 256;
            float s2 = 0.f;
#pragma unroll
            for (int kk = 0; kk < 8; kk++) s2 += hid[lane + kk * 32] * lr[lane + kk * 32];
#pragma unroll
            for (int o = 16; o; o >>= 1) s2 += __shfl_xor_sync(0xffffffffu, s2, o);
            if (lane == 0) out[b * Cx + cc] = s2 + lin_b[cc];
        }
    }
}

extern "C" void kernel_launch(void* const* d_in, const int* in_sizes, int n_in,
                              void* d_out, int out_size) {
    const int* wordid   = (const int*)d_in[0];
    const float* c0     = (const float*)d_in[2];
    const float* emb    = (const float*)d_in[3];
    const float* W_iou  = (const float*)d_in[4];
    const float* U_iou  = (const float*)d_in[5];
    const float* b_iou  = (const float*)d_in[6];
    const float* Uf_W   = (const float*)d_in[7];
    const float* Uf_b   = (const float*)d_in[8];
    const float* Wmem   = (const float*)d_in[9];
    const float* wh_W   = (const float*)d_in[10];
    const float* wh_b   = (const float*)d_in[11];
    const float* lin_W  = (const float*)d_in[12];
    const float* lin_b  = (const float*)d_in[13];
    float* out = (float*)d_out;
    (void)in_sizes; (void)n_in; (void)out_size;

    const int SMEM0 = NSTAGE * (128 + 192) * ROWB;   // 184320
    const int SMEM1 = NSTAGE * (128 + 160) * ROWB;   // 165888
    cudaFuncSetAttribute(tabgemm_k, cudaFuncAttributeMaxDynamicSharedMemorySize,
                         SMEM0);
    cudaFuncSetAttribute(hgemm_lvl_k, cudaFuncAttributeMaxDynamicSharedMemorySize,
                         SMEM1);
    cudaFuncSetAttribute(plevels_k, cudaFuncAttributeMaxDynamicSharedMemorySize,
                         SMEM1);

    // fp16 mirrors (gate-interleaved weights) + barrier reset
    emb16_k<<<(Vx * Xx + 255) / 256, 256>>>(emb);
    wiou16_k<<<(GH3 * Xx + 255) / 256, 256>>>(W_iou);
    wc16_k<<<(NC * K2H + 255) / 256, 256>>>(Uf_W, U_iou);
    reset_bar_k<<<1, 1>>>();

    // Table: tab = emb @ W_iou^T
    tabgemm_k<<<dim3(Vx / 128, GH3 / 192), 256, SMEM0>>>();

    // Leaves: gather table rows + node math
    leaf_from_tab_k<<<(Bx * NLEAF * 128 + 255) / 256, 256>>>(wordid, c0, b_iou);

    // Levels 8..5: per-level launches (grids exceed resident capacity)
    for (int level = 8; level >= 5; level--) {
        int npar = 1 << level, ps = npar - 1;
        hgemm_lvl_k<<<dim3(npar, NC / 160), 256, SMEM1>>>(b_iou, Uf_b, ps, level);
    }
    // Levels 4..0: persistent kernel, 128 CTAs, device-wide barrier
    plevels_k<<<dim3(16, NC / 160), 256, SMEM1>>>(b_iou, Uf_b);

    // Attention + head (fused)
    attn_all_k<<<Bx, 1024>>>(Wmem, wh_W, wh_b, lin_W, lin_b, out);
}

// round 17
// speedup vs baseline: 1.1620x; 1.0069x over previous
#include <cuda_runtime.h>
#include <cuda_fp16.h>
#include <math.h>
#include <stdint.h>

#define Bx 128
#define Nx 1023
#define Hx 256
#define Xx 256
#define Cx 10
#define Vx 32000
#define NLEAF 512
#define GH3 768      // 3*H
#define NC 1280      // 2H (f gates) + 3H (iou)
#define K2H 512      // 2*H

// ---- device-global scratch (no allocations allowed) ----
__device__ __half g_h16[(size_t)Bx * Nx * Hx];        // fp16 h (GEMM A + attention)
__device__ float g_c[(size_t)Bx * Nx * Hx];           // fp32 c
__device__ __half g_emb16[(size_t)Vx * Xx];
__device__ __half g_tab[(size_t)Vx * GH3];            // emb @ W_iou^T (interleaved)
__device__ __half g_Wc16[NC * K2H];     // gate-interleaved [f1,f2,i,o,u]x8 groups
__device__ __half g_Wiou16[GH3 * Xx];   // gate-interleaved [i,o,u]x8 groups
__device__ int g_bar;                   // device-wide barrier counter

// fast transcendentals: MUFU-based, rel err ~1e-6
__device__ __forceinline__ float sigm(float x) {
    return __fdividef(1.f, 1.f + __expf(-x));
}
__device__ __forceinline__ float ftanh(float x) {
    x = fminf(fmaxf(x, -15.f), 15.f);
    float e = __expf(2.f * x);
    return __fdividef(e - 1.f, e + 1.f);
}

#define LDSM4(r0, r1, r2, r3, addr)                                          \
    asm volatile("ldmatrix.sync.aligned.m8n8.x4.shared.b16 {%0,%1,%2,%3}, [%4];" \
                 : "=r"(r0), "=r"(r1), "=r"(r2), "=r"(r3) : "r"(addr))
#define LDSM2(r0, r1, addr)                                                  \
    asm volatile("ldmatrix.sync.aligned.m8n8.x2.shared.b16 {%0,%1}, [%2];"   \
                 : "=r"(r0), "=r"(r1) : "r"(addr))

#define HMMA(d, a, b0, b1)                                                   \
    asm volatile(                                                            \
        "mma.sync.aligned.m16n8k16.row.col.f32.f16.f16.f32 "                 \
        "{%0,%1,%2,%3}, {%4,%5,%6,%7}, {%8,%9}, {%0,%1,%2,%3};"              \
        : "+f"(d[0]), "+f"(d[1]), "+f"(d[2]), "+f"(d[3])                     \
        : "r"(a[0]), "r"(a[1]), "r"(a[2]), "r"(a[3]), "r"(b0), "r"(b1))

#define CP16(dst, src)                                                       \
    asm volatile("cp.async.cg.shared.global [%0], [%1], 16;" ::"r"(dst),     \
                 "l"(src))
#define CPCOMMIT() asm volatile("cp.async.commit_group;")
#define CPWAIT(n) asm volatile("cp.async.wait_group %0;" ::"n"(n))

__device__ __forceinline__ uint32_t smem_u32(const void* p) {
    uint32_t a;
    asm("{ .reg .u64 t; cvta.to.shared.u64 t, %1; cvt.u32.u64 %0, t; }"
        : "=r"(a) : "l"(p));
    return a;
}

// ---- fp16 mirror setup (with gate interleave) ----
__global__ void emb16_k(const float* __restrict__ emb) {
    int i = blockIdx.x * 256 + threadIdx.x;
    if (i < Vx * Xx) g_emb16[i] = __float2half(emb[i]);
}
__global__ void wiou16_k(const float* __restrict__ W_iou) {
    int i = blockIdx.x * 256 + threadIdx.x;
    if (i >= GH3 * Xx) return;
    int r = i >> 8, k = i & 255;
    int w = r % 24, gate = w >> 3, j = (r / 24) * 8 + (w & 7);
    g_Wiou16[i] = __float2half(W_iou[(gate * 256 + j) * Xx + k]);
}
__global__ void wc16_k(const float* __restrict__ Uf_W,
                       const float* __restrict__ U_iou) {
    int i = blockIdx.x * 256 + threadIdx.x;
    if (i >= NC * K2H) return;
    int r = i >> 9, k = i & 511;
    int w = r % 40, gate = w >> 3, j = (r / 40) * 8 + (w & 7);
    float v = (gate < 2) ? Uf_W[(gate * 256 + j) * K2H + k]
                         : U_iou[((gate - 2) * 256 + j) * K2H + k];
    g_Wc16[i] = __float2half(v);
}
__global__ void reset_bar_k() { g_bar = 0; }

#define ROWB 144
#define ABYTES (128 * ROWB)
#define NSTAGE 4

// ===================================================================
// Level GEMM+node body (shared by per-level kernel and persistent
// small-levels kernel). NBLK=160, warp 64x40, K=512, 4-stage ring.
// ===================================================================
__device__ __forceinline__ void level_body(
    char* smem, const float* __restrict__ b_iou,
    const float* __restrict__ Uf_b, int mtile, int ntile, int ps, int shift) {
    constexpr int NBLK = 160;
    constexpr int NI = 5;
    constexpr int WN = 40;
    constexpr int STAGEB = (128 + NBLK) * ROWB;
    const uint32_t sb = smem_u32(smem);
    const int tid = threadIdx.x, lane = tid & 31, warp = tid >> 5;
    const int rowStart = mtile * 128, colStart = ntile * NBLK;
    const int warpM = warp >> 2, warpN = warp & 3;
    const int mask = (1 << shift) - 1;

    const int sr = tid >> 1;
    const __half* ap;
    {
        int r = rowStart + sr;
        int b = r >> shift, pl = r & mask;
        ap = g_h16 + ((size_t)(b * Nx + 2 * (ps + pl) + 1)) * Hx + (tid & 1) * 32;
    }
    const __half* bp = g_Wc16 + (size_t)(colStart + (tid < NBLK ? tid : 0)) * K2H;
    const uint32_t adst0 = sb + sr * ROWB + (tid & 1) * 64;
    const uint32_t bdst0 = sb + ABYTES + (tid < NBLK ? tid : 0) * ROWB;
    const bool doB = (tid < NBLK);

    const int aRow = warpM * 64 + (lane & 7) + ((lane >> 3) & 1) * 8;
    const int aK = (lane >> 4) * 8;
    const int bRow = warpN * WN + (lane & 7) + ((lane >> 4) & 1) * 8;
    const int bK = ((lane >> 3) & 1) * 8;
    const uint32_t aA0 = sb + aRow * ROWB + aK * 2;
    const uint32_t bA0 = sb + ABYTES + bRow * ROWB + bK * 2;
    const int l15 = lane & 15;
    const uint32_t b2A0 =
        sb + ABYTES + (warpN * WN + 32 + (l15 & 7)) * ROWB + (l15 >> 3) * 16;

    float acc[4][NI][4];
#pragma unroll
    for (int mi = 0; mi < 4; mi++)
#pragma unroll
        for (int ni = 0; ni < NI; ni++)
#pragma unroll
            for (int cc = 0; cc < 4; cc++) acc[mi][ni][cc] = 0.f;

    const int nch = K2H / 64;   // 8

#pragma unroll
    for (int s = 0; s < 3; s++) {
        const uint32_t ad = adst0 + s * STAGEB;
        const __half* ag = ap + s * 64;
        CP16(ad, ag); CP16(ad + 16, ag + 8);
        CP16(ad + 32, ag + 16); CP16(ad + 48, ag + 24);
        if (doB) {
            const uint32_t bd = bdst0 + s * STAGEB;
            const __half* bg = bp + s * 64;
            CP16(bd, bg); CP16(bd + 16, bg + 8);
            CP16(bd + 32, bg + 16); CP16(bd + 48, bg + 24);
            CP16(bd + 64, bg + 32); CP16(bd + 80, bg + 40);
            CP16(bd + 96, bg + 48); CP16(bd + 112, bg + 56);
        }
        CPCOMMIT();
    }

    for (int ci = 0; ci < nch; ci++) {
        const int rem = nch - 1 - ci;
        if (rem >= 2) { CPWAIT(2); }
        else if (rem == 1) { CPWAIT(1); }
        else { CPWAIT(0); }
        __syncthreads();
        if (ci + 3 < nch) {
            const int s = (ci + 3) & 3;
            const uint32_t ad = adst0 + s * STAGEB;
            const __half* ag = ap + (ci + 3) * 64;
            CP16(ad, ag); CP16(ad + 16, ag + 8);
            CP16(ad + 32, ag + 16); CP16(ad + 48, ag + 24);
            if (doB) {
                const uint32_t bd = bdst0 + s * STAGEB;
                const __half* bg = bp + (ci + 3) * 64;
                CP16(bd, bg); CP16(bd + 16, bg + 8);
                CP16(bd + 32, bg + 16); CP16(bd + 48, bg + 24);
                CP16(bd + 64, bg + 32); CP16(bd + 80, bg + 40);
                CP16(bd + 96, bg + 48); CP16(bd + 112, bg + 56);
            }
            CPCOMMIT();
        }
        const int slot = ci & 3;
        const uint32_t ab = aA0 + slot * STAGEB;
        const uint32_t bb = bA0 + slot * STAGEB;
        const uint32_t bb2 = b2A0 + slot * STAGEB;
#pragma unroll
        for (int ks = 0; ks < 4; ks++) {
            uint32_t aF[4][4], bq[2 * NI];
#pragma unroll
            for (int mi = 0; mi < 4; mi++)
                LDSM4(aF[mi][0], aF[mi][1], aF[mi][2], aF[mi][3],
                      ab + mi * (16 * ROWB) + ks * 32);
            LDSM4(bq[0], bq[1], bq[2], bq[3], bb + ks * 32);
            LDSM4(bq[4], bq[5], bq[6], bq[7], bb + 16 * ROWB + ks * 32);
            LDSM2(bq[8], bq[9], bb2 + ks * 32);
#pragma unroll
            for (int mi = 0; mi < 4; mi++)
#pragma unroll
                for (int ni = 0; ni < NI; ni++)
                    HMMA(acc[mi][ni], aF[mi], bq[2 * ni], bq[2 * ni + 1]);
        }
    }

    const int g = lane >> 2, tt = lane & 3;
    const int jb = (ntile * 4 + warpN) * 8 + tt * 2;
    const float bf10 = Uf_b[jb], bf11 = Uf_b[jb + 1];
    const float bf20 = Uf_b[256 + jb], bf21 = Uf_b[257 + jb];
    const float bi0 = b_iou[jb], bi1 = b_iou[jb + 1];
    const float bo0 = b_iou[256 + jb], bo1 = b_iou[257 + jb];
    const float bu0 = b_iou[512 + jb], bu1 = b_iou[513 + jb];
#pragma unroll
    for (int mi = 0; mi < 4; mi++) {
#pragma unroll
        for (int hf = 0; hf < 2; hf++) {
            const int r = rowStart + warpM * 64 + mi * 16 + g + hf * 8;
            const int b = r >> shift, pl = r & mask;
            const int p = ps + pl;
            const size_t cidx = ((size_t)(b * Nx + 2 * p + 1)) * Hx + jb;
            const float2 c1 = *(const float2*)(g_c + cidx);
            const float2 c2 = *(const float2*)(g_c + cidx + Hx);
            const float f10 = sigm(acc[mi][0][hf * 2 + 0] + bf10);
            const float f11 = sigm(acc[mi][0][hf * 2 + 1] + bf11);
            const float f20 = sigm(acc[mi][1][hf * 2 + 0] + bf20);
            const float f21 = sigm(acc[mi][1][hf * 2 + 1] + bf21);
            const float cs0 = f10 * c1.x + f20 * c2.x;
            const float cs1 = f11 * c1.y + f21 * c2.y;
            const float iv0 = acc[mi][2][hf * 2 + 0] + bi0;
            const float iv1 = acc[mi][2][hf * 2 + 1] + bi1;
            const float ov0 = acc[mi][3][hf * 2 + 0] + bo0;
            const float ov1 = acc[mi][3][hf * 2 + 1] + bo1;
            const float uv0 = acc[mi][4][hf * 2 + 0] + bu0;
            const float uv1 = acc[mi][4][hf * 2 + 1] + bu1;
            const float cA = sigm(iv0) * ftanh(uv0) + cs0;
            const float cB = sigm(iv1) * ftanh(uv1) + cs1;
            const float hA = sigm(ov0) * ftanh(cA);
            const float hB = sigm(ov1) * ftanh(cB);
            const size_t pidx = ((size_t)(b * Nx + p)) * Hx + jb;
            *(float2*)(g_c + pidx) = make_float2(cA, cB);
            *(__half2*)(g_h16 + pidx) = __floats2half2_rn(hA, hB);
        }
    }
}

// ---- per-level kernel (levels 8..5) ----
__global__ __launch_bounds__(256, 1) void hgemm_lvl_k(
    const float* __restrict__ b_iou, const float* __restrict__ Uf_b,
    int ps, int shift) {
    extern __shared__ char smem[];
    level_body(smem, b_iou, Uf_b, blockIdx.x, blockIdx.y, ps, shift);
}

// ---- persistent kernel: levels 4..0 with device-wide phase barrier ----
// grid (16,8) = 128 CTAs, all resident (1 CTA/SM, 148 SMs).
__global__ __launch_bounds__(256, 1) void plevels_k(
    const float* __restrict__ b_iou, const float* __restrict__ Uf_b) {
    extern __shared__ char smem[];
    int target = 0;
    for (int level = 4; level >= 0; level--) {
        const int npar = 1 << level;
        if ((int)blockIdx.x < npar) {
            level_body(smem, b_iou, Uf_b, blockIdx.x, blockIdx.y,
                       npar - 1, level);
        }
        if (level > 0) {
            target += 128;
            __threadfence();
            __syncthreads();
            if (threadIdx.x == 0) {
                atomicAdd(&g_bar, 1);
                while (atomicAdd(&g_bar, 0) < target) __nanosleep(200);
            }
            __syncthreads();
            __threadfence();
        }
    }
}

// ===================================================================
// Table GEMM: tab = emb @ W_iou^T (M=32000, N=768 via NBLK=192, K=256)
// ===================================================================
__global__ __launch_bounds__(256, 1) void tabgemm_k() {
    constexpr int NBLK = 192;
    constexpr int NI = 6;
    constexpr int WN = 48;
    constexpr int STAGEB = (128 + NBLK) * ROWB;
    extern __shared__ char smem[];
    const uint32_t sb = smem_u32(smem);
    const int tid = threadIdx.x, lane = tid & 31, warp = tid >> 5;
    const int rowStart = blockIdx.x * 128, colStart = blockIdx.y * NBLK;
    const int warpM = warp >> 2, warpN = warp & 3;

    const int sr = tid >> 1;
    const __half* ap = g_emb16 + (size_t)(rowStart + sr) * Xx + (tid & 1) * 32;
    const __half* bp = g_Wiou16 + (size_t)(colStart + (tid < NBLK ? tid : 0)) * Xx;
    const uint32_t adst0 = sb + sr * ROWB + (tid & 1) * 64;
    const uint32_t bdst0 = sb + ABYTES + (tid < NBLK ? tid : 0) * ROWB;
    const bool doB = (tid < NBLK);

    const int aRow = warpM * 64 + (lane & 7) + ((lane >> 3) & 1) * 8;
    const int aK = (lane >> 4) * 8;
    const int bRow = warpN * WN + (lane & 7) + ((lane >> 4) & 1) * 8;
    const int bK = ((lane >> 3) & 1) * 8;
    const uint32_t aA0 = sb + aRow * ROWB + aK * 2;
    const uint32_t bA0 = sb + ABYTES + bRow * ROWB + bK * 2;

    float acc[4][NI][4];
#pragma unroll
    for (int mi = 0; mi < 4; mi++)
#pragma unroll
        for (int ni = 0; ni < NI; ni++)
#pragma unroll
            for (int cc = 0; cc < 4; cc++) acc[mi][ni][cc] = 0.f;

    const int nch = Xx / 64;   // 4

#pragma unroll
    for (int s = 0; s < 3; s++) {
        const uint32_t ad = adst0 + s * STAGEB;
        const __half* ag = ap + s * 64;
        CP16(ad, ag); CP16(ad + 16, ag + 8);
        CP16(ad + 32, ag + 16); CP16(ad + 48, ag + 24);
        if (doB) {
            const uint32_t bd = bdst0 + s * STAGEB;
            const __half* bg = bp + s * 64;
            CP16(bd, bg); CP16(bd + 16, bg + 8);
            CP16(bd + 32, bg + 16); CP16(bd + 48, bg + 24);
            CP16(bd + 64, bg + 32); CP16(bd + 80, bg + 40);
            CP16(bd + 96, bg + 48); CP16(bd + 112, bg + 56);
        }
        CPCOMMIT();
    }

    for (int ci = 0; ci < nch; ci++) {
        const int rem = nch - 1 - ci;
        if (rem >= 2) { CPWAIT(2); }
        else if (rem == 1) { CPWAIT(1); }
        else { CPWAIT(0); }
        __syncthreads();
        if (ci + 3 < nch) {
            const int s = (ci + 3) & 3;
            const uint32_t ad = adst0 + s * STAGEB;
            const __half* ag = ap + (ci + 3) * 64;
            CP16(ad, ag); CP16(ad + 16, ag + 8);
            CP16(ad + 32, ag + 16); CP16(ad + 48, ag + 24);
            if (doB) {
                const uint32_t bd = bdst0 + s * STAGEB;
                const __half* bg = bp + (ci + 3) * 64;
                CP16(bd, bg); CP16(bd + 16, bg + 8);
                CP16(bd + 32, bg + 16); CP16(bd + 48, bg + 24);
                CP16(bd + 64, bg + 32); CP16(bd + 80, bg + 40);
                CP16(bd + 96, bg + 48); CP16(bd + 112, bg + 56);
            }
            CPCOMMIT();
        }
        const int slot = ci & 3;
        const uint32_t ab = aA0 + slot * STAGEB;
        const uint32_t bb = bA0 + slot * STAGEB;
#pragma unroll
        for (int ks = 0; ks < 4; ks++) {
            uint32_t aF[4][4], bq[2 * NI];
#pragma unroll
            for (int mi = 0; mi < 4; mi++)
                LDSM4(aF[mi][0], aF[mi][1], aF[mi][2], aF[mi][3],
                      ab + mi * (16 * ROWB) + ks * 32);
            LDSM4(bq[0], bq[1], bq[2], bq[3], bb + ks * 32);
            LDSM4(bq[4], bq[5], bq[6], bq[7], bb + 16 * ROWB + ks * 32);
            LDSM4(bq[8], bq[9], bq[10], bq[11], bb + 32 * ROWB + ks * 32);
#pragma unroll
            for (int mi = 0; mi < 4; mi++)
#pragma unroll
                for (int ni = 0; ni < NI; ni++)
                    HMMA(acc[mi][ni], aF[mi], bq[2 * ni], bq[2 * ni + 1]);
        }
    }

    const int g = lane >> 2, tt = lane & 3;
#pragma unroll
    for (int mi = 0; mi < 4; mi++)
#pragma unroll
        for (int ni = 0; ni < NI; ni++) {
            const int row = rowStart + warpM * 64 + mi * 16 + g;
            const int col = colStart + warpN * WN + ni * 8 + tt * 2;
            *(__half2*)(g_tab + (size_t)row * GH3 + col) =
                __floats2half2_rn(acc[mi][ni][0], acc[mi][ni][1]);
            *(__half2*)(g_tab + (size_t)(row + 8) * GH3 + col) =
                __floats2half2_rn(acc[mi][ni][2], acc[mi][ni][3]);
        }
}

// ===================================================================
// Leaf-from-table: gather precomputed iou preacts, apply node math.
// ===================================================================
__global__ void leaf_from_tab_k(const int* __restrict__ wordid,
                                const float* __restrict__ c0,
                                const float* __restrict__ b_iou) {
    int i = blockIdx.x * 256 + threadIdx.x;
    if (i >= Bx * NLEAF * 128) return;
    const int up = i & 127;       // unit pair index
    const int rl = i >> 7;        // b*512 + l
    const int b = rl >> 9, l = rl & 511;
    const int j = up * 2;
    const int gi = j >> 3, wi = j & 7;
    const int w = wordid[b * Nx + (NLEAF - 1) + l];
    const __half* row = g_tab + (size_t)w * GH3 + gi * 24;
    const float2 fi = __half22float2(*(const __half2*)(row + wi));
    const float2 fo = __half22float2(*(const __half2*)(row + 8 + wi));
    const float2 fu = __half22float2(*(const __half2*)(row + 16 + wi));
    const float iv0 = fi.x + b_iou[j], iv1 = fi.y + b_iou[j + 1];
    const float ov0 = fo.x + b_iou[256 + j], ov1 = fo.y + b_iou[257 + j];
    const float uv0 = fu.x + b_iou[512 + j], uv1 = fu.y + b_iou[513 + j];
    const size_t idx = ((size_t)(b * Nx + (NLEAF - 1) + l)) * Hx + j;
    const float2 cz = *(const float2*)(c0 + idx);
    const float cA = sigm(iv0) * ftanh(uv0) + cz.x;
    const float cB = sigm(iv1) * ftanh(uv1) + cz.y;
    const float hA = sigm(ov0) * ftanh(cA);
    const float hB = sigm(ov1) * ftanh(cB);
    *(float2*)(g_c + idx) = make_float2(cA, cB);
    *(__half2*)(g_h16 + idx) = __floats2half2_rn(hA, hB);
}

// ===================================================================
// Fused attention + head: q = Wmem^T dec; scores=q.h; softmax; ctx;
// hid = relu(ctx Wh^T + b); out = hid lin^T + b.  One CTA per batch b.
// ===================================================================
__global__ __launch_bounds__(1024) void attn_all_k(
    const float* __restrict__ Wmem, const float* __restrict__ wh_W,
    const float* __restrict__ wh_b, const float* __restrict__ lin_W,
    const float* __restrict__ lin_b, float* __restrict__ out) {
    __shared__ float dec[256];
    __shared__ float q[256];
    __shared__ float sc[1024];
    __shared__ float red[32];
    __shared__ float part[4][256];
    __shared__ float stat[2];
    __shared__ float ctx[256];
    __shared__ float hid[256];
    int b = blockIdx.x, tid = threadIdx.x;
    int warp = tid >> 5, lane = tid & 31;
    const __half* hb = g_h16 + (size_t)b * Nx * Hx;
    if (tid < 256) dec[tid] = __half2float(hb[tid]);   // h[b, node 0]
    __syncthreads();
    // q[h] = sum_g dec[g] * Wmem[g*256+h], 4 partial slices
    {
        int h = tid & 255, pt = tid >> 8;
        float s = 0.f;
        const float* wm = Wmem + (size_t)(pt * 64) * 256 + h;
#pragma unroll 8
        for (int g = 0; g < 64; g++) s += dec[pt * 64 + g] * wm[g * 256];
        part[pt][h] = s;
    }
    __syncthreads();
    if (tid < 256) q[tid] = part[0][tid] + part[1][tid] + part[2][tid] + part[3][tid];
    __syncthreads();
    // scores
    for (int n = warp; n < Nx; n += 32) {
        const __half2* hr2 = (const __half2*)(hb + (size_t)n * Hx);
        float s = 0.f;
#pragma unroll
        for (int kk = 0; kk < 4; kk++) {
            int i2 = lane + kk * 32;
            float2 f = __half22float2(hr2[i2]);
            s += q[2 * i2] * f.x + q[2 * i2 + 1] * f.y;
        }
#pragma unroll
        for (int o = 16; o; o >>= 1) s += __shfl_xor_sync(0xffffffffu, s, o);
        if (lane == 0) sc[n] = s;
    }
    __syncthreads();
    float sraw = (tid < Nx) ? sc[tid] : -3.4e38f;
    float v = sraw;
#pragma unroll
    for (int o = 16; o; o >>= 1) v = fmaxf(v, __shfl_xor_sync(0xffffffffu, v, o));
    if (lane == 0) red[warp] = v;
    __syncthreads();
    if (warp == 0) {
        float m = red[lane];
#pragma unroll
        for (int o = 16; o; o >>= 1) m = fmaxf(m, __shfl_xor_sync(0xffffffffu, m, o));
        if (lane == 0) stat[0] = m;
    }
    __syncthreads();
    float m = stat[0];
    float e = (tid < Nx) ? __expf(sraw - m) : 0.f;
    sc[tid] = e;
    float s = e;
#pragma unroll
    for (int o = 16; o; o >>= 1) s += __shfl_xor_sync(0xffffffffu, s, o);
    if (lane == 0) red[warp] = s;
    __syncthreads();
    if (warp == 0) {
        float S = red[lane];
#pragma unroll
        for (int o = 16; o; o >>= 1) S += __shfl_xor_sync(0xffffffffu, S, o);
        if (lane == 0) stat[1] = S;
    }
    __syncthreads();
    float Sinv = __fdividef(1.f, stat[1]);
    {
        int grp = tid >> 8, j = tid & 255;
        float p = 0.f;
        for (int n = grp; n < Nx; n += 4)
            p += sc[n] * __half2float(hb[(size_t)n * Hx + j]);
        part[grp][j] = p;
    }
    __syncthreads();
    if (tid < 256)
        ctx[tid] = (part[0][tid] + part[1][tid] + part[2][tid] + part[3][tid]) * Sinv;
    __syncthreads();
    // head
    for (int h = warp; h < 256; h += 32) {
        const float* wr = wh_W + (size_t)h * 256;
        float s2 = 0.f;
#pragma unroll
        for (int kk = 0; kk < 8; kk++) s2 += ctx[lane + kk * 32] * wr[lane + kk * 32];
#pragma unroll
        for (int o = 16; o; o >>= 1) s2 += __shfl_xor_sync(0xffffffffu, s2, o);
        if (lane == 0) hid[h] = fmaxf(s2 + wh_b[h], 0.f);
    }
    __syncthreads();
    if (warp == 0) {
        for (int cc = 0; cc < Cx; cc++) {
            const float* lr = lin_W + (size_t)cc * 256;
            float s2 = 0.f;
#pragma unroll
            for (int kk = 0; kk < 8; kk++) s2 += hid[lane + kk * 32] * lr[lane + kk * 32];
#pragma unroll
            for (int o = 16; o; o >>= 1) s2 += __shfl_xor_sync(0xffffffffu, s2, o);
            if (lane == 0) out[b * Cx + cc] = s2 + lin_b[cc];
        }
    }
}

extern "C" void kernel_launch(void* const* d_in, const int* in_sizes, int n_in,
                              void* d_out, int out_size) {
    const int* wordid   = (const int*)d_in[0];
    const float* c0     = (const float*)d_in[2];
    const float* emb    = (const float*)d_in[3];
    const float* W_iou  = (const float*)d_in[4];
    const float* U_iou  = (const float*)d_in[5];
    const float* b_iou  = (const float*)d_in[6];
    const float* Uf_W   = (const float*)d_in[7];
    const float* Uf_b   = (const float*)d_in[8];
    const float* Wmem   = (const float*)d_in[9];
    const float* wh_W   = (const float*)d_in[10];
    const float* wh_b   = (const float*)d_in[11];
    const float* lin_W  = (const float*)d_in[12];
    const float* lin_b  = (const float*)d_in[13];
    float* out = (float*)d_out;
    (void)in_sizes; (void)n_in; (void)out_size;

    const int SMEM0 = NSTAGE * (128 + 192) * ROWB;   // 184320
    const int SMEM1 = NSTAGE * (128 + 160) * ROWB;   // 165888
    cudaFuncSetAttribute(tabgemm_k, cudaFuncAttributeMaxDynamicSharedMemorySize,
                         SMEM0);
    cudaFuncSetAttribute(hgemm_lvl_k, cudaFuncAttributeMaxDynamicSharedMemorySize,
                         SMEM1);
    cudaFuncSetAttribute(plevels_k, cudaFuncAttributeMaxDynamicSharedMemorySize,
                         SMEM1);

    // fp16 mirrors (gate-interleaved weights) + barrier reset
    emb16_k<<<(Vx * Xx + 255) / 256, 256>>>(emb);
    wiou16_k<<<(GH3 * Xx + 255) / 256, 256>>>(W_iou);
    wc16_k<<<(NC * K2H + 255) / 256, 256>>>(Uf_W, U_iou);
    reset_bar_k<<<1, 1>>>();

    // Table: tab = emb @ W_iou^T
    tabgemm_k<<<dim3(Vx / 128, GH3 / 192), 256, SMEM0>>>();

    // Leaves: gather table rows + node math
    leaf_from_tab_k<<<(Bx * NLEAF * 128 + 255) / 256, 256>>>(wordid, c0, b_iou);

    // Levels 8..5: per-level launches (grids exceed resident capacity)
    for (int level = 8; level >= 5; level--) {
        int npar = 1 << level, ps = npar - 1;
        hgemm_lvl_k<<<dim3(npar, NC / 160), 256, SMEM1>>>(b_iou, Uf_b, ps, level);
    }
    // Levels 4..0: persistent kernel, 128 CTAs, device-wide barrier
    plevels_k<<<dim3(16, NC / 160), 256, SMEM1>>>(b_iou, Uf_b);

    // Attention + head (fused)
    attn_all_k<<<Bx, 1024>>>(Wmem, wh_W, wh_b, lin_W, lin_b, out);
}